// round 11
// baseline (speedup 1.0000x reference)
#include <cuda_runtime.h>
#include <cstdint>
#include <math.h>
#include <complex>

// Problem constants
#define S_LEN 128
#define B_SZ  128
#define H_DIM 8
#define T_OUT 12
#define NROWS (S_LEN * B_SZ)
#define N_RAW 30
#define MAX_EMIT 40

#define SM_COUNT 148
#define SCAN_SLOTS 32
#define BLOCKS_PER_SM 8
#define GRID_BLOCKS (SM_COUNT * BLOCKS_PER_SM)

// ---------------------------------------------------------------------------
// Device scratch
// ---------------------------------------------------------------------------
__device__ float g_zx[NROWS * 32];
__device__ float g_h[NROWS * H_DIM];
__device__ int   g_flag[NROWS];
__device__ int   g_ticket;

struct QU { float u[MAX_EMIT * 8]; };   // fused-op coefficients, host-computed

// ---------------------------------------------------------------------------
// Compile-time MT19937 + random-layer structure (types/wires only; no floats).
// ---------------------------------------------------------------------------
struct EmitList { int n; int type[MAX_EMIT]; int a[MAX_EMIT]; int b[MAX_EMIT]; };

constexpr uint32_t cmt_next(uint32_t (&mt)[624], int& mti) {
    if (mti >= 624) {
        for (int i = 0; i < 624; i++) {
            uint32_t y = (mt[i] & 0x80000000u) | (mt[(i + 1) % 624] & 0x7fffffffu);
            mt[i] = mt[(i + 397) % 624] ^ (y >> 1) ^ ((y & 1u) ? 0x9908b0dfu : 0u);
        }
        mti = 0;
    }
    uint32_t y = mt[mti++];
    y ^= y >> 11;
    y ^= (y << 7) & 0x9d2c5680u;
    y ^= (y << 15) & 0xefc60000u;
    y ^= y >> 18;
    return y;
}
constexpr uint32_t c_randint(uint32_t (&mt)[624], int& mti, uint32_t n) {
    uint32_t rng = n - 1;
    uint32_t mask = rng;
    mask |= mask >> 1; mask |= mask >> 2; mask |= mask >> 4;
    mask |= mask >> 8; mask |= mask >> 16;
    uint32_t v = cmt_next(mt, mti) & mask;
    while (v > rng) v = cmt_next(mt, mti) & mask;
    return v;
}

constexpr EmitList compute_emitted() {
    uint32_t mt[624] = {};
    mt[0] = 1234u;
    for (int i = 1; i < 624; i++)
        mt[i] = 1812433253u * (mt[i - 1] ^ (mt[i - 1] >> 30)) + (uint32_t)i;
    int mti = 624;

    EmitList E{};
    int cnt[8] = {};
    bool allrz[8] = {true, true, true, true, true, true, true, true};

    for (int k = 0; k < N_RAW; k++) {
        uint32_t kind = c_randint(mt, mti, 4);
        if (kind == 3) {
            int c = (int)c_randint(mt, mti, 8);
            int t = (int)c_randint(mt, mti, 7);
            if (t >= c) t++;
            if (cnt[c]) { E.type[E.n] = allrz[c] ? 2 : 0; E.a[E.n] = c; E.b[E.n] = 0; E.n++; cnt[c] = 0; allrz[c] = true; }
            if (cnt[t]) { E.type[E.n] = allrz[t] ? 2 : 0; E.a[E.n] = t; E.b[E.n] = 0; E.n++; cnt[t] = 0; allrz[t] = true; }
            E.type[E.n] = 1; E.a[E.n] = c; E.b[E.n] = t; E.n++;
        } else {
            int g = (int)(kind % 3);
            int w = (int)c_randint(mt, mti, 8);
            cmt_next(mt, mti); cmt_next(mt, mti);   // uniform() draws
            cnt[w]++;
            if (g != 2) allrz[w] = false;
        }
    }
    for (int w = 0; w < 8; w++)
        if (cnt[w]) { E.type[E.n] = allrz[w] ? 2 : 0; E.a[E.n] = w; E.b[E.n] = 0; E.n++; }
    return E;
}

constexpr EmitList EM = compute_emitted();

// ---------------------------------------------------------------------------
// Fast helpers
// ---------------------------------------------------------------------------
__device__ __forceinline__ float fast_rcp(float x){ float r; asm("rcp.approx.f32 %0,%1;":"=f"(r):"f"(x)); return r; }
__device__ __forceinline__ float fast_ex2(float x){ float r; asm("ex2.approx.f32 %0,%1;":"=f"(r):"f"(x)); return r; }
__device__ __forceinline__ float fast_exp(float x){ return fast_ex2(x * 1.4426950408889634f); }
__device__ __forceinline__ float fast_sigmoid(float x){ return fast_rcp(1.f + fast_exp(-x)); }
__device__ __forceinline__ float fast_tanh(float x){
    x = fminf(fmaxf(x, -9.f), 9.f);
    float e = fast_exp(2.f * x);
    return (e - 1.f) * fast_rcp(e + 1.f);
}
__device__ __forceinline__ int ld_acquire(const int* p){
    int v; asm volatile("ld.acquire.gpu.global.b32 %0,[%1];":"=r"(v):"l"(p):"memory"); return v;
}
__device__ __forceinline__ void st_release(int* p, int v){
    asm volatile("st.release.gpu.global.b32 [%0],%1;"::"l"(p),"r"(v):"memory");
}

// ---------------------------------------------------------------------------
// Kernel 1: zx + flag/ticket clearing. 2 rows per warp (MLP=2).
// ---------------------------------------------------------------------------
__global__ __launch_bounds__(256) void zx_kernel(
    const float* __restrict__ emb, const float* __restrict__ Win,
    const float* __restrict__ b_in, const float* __restrict__ phi,
    const int* __restrict__ sent32)
{
    __shared__ float4 sW4[32 * 17];
    __shared__ float4 sx4[16 * 17];
    __shared__ float  sBP[32];
    __shared__ int    sIs64;

    int tid = threadIdx.x, lane = tid & 31, wid = tid >> 5;
    int gid = blockIdx.x * 256 + tid;
    if (gid < NROWS) g_flag[gid] = 0;
    if (gid == 0) g_ticket = 0;

    if (wid == 0) {
        int acc = sent32[2 * lane + 1] | sent32[2 * (lane + 32) + 1];
        #pragma unroll
        for (int off = 16; off; off >>= 1) acc |= __shfl_xor_sync(~0u, acc, off);
        if (lane == 0) sIs64 = (acc == 0) ? 1 : 0;
    }
    for (int i = tid; i < 512; i += 256) {
        int t = i >> 4, k = i & 15;
        sW4[t * 17 + k] = ((const float4*)(Win + t * 72))[k];
    }
    if (tid < 32) sBP[tid] = b_in[tid] + phi[tid];
    __syncthreads();

    int m0 = blockIdx.x * 16 + wid * 2;
    int half = lane >> 4;
    int m = m0 + half;
    int tok = sIs64 ? sent32[2 * m] : sent32[m];
    sx4[(wid * 2 + half) * 17 + (lane & 15)] =
        ((const float4*)(emb + (size_t)tok * 64))[lane & 15];
    __syncwarp();

    int t = lane;
    float bp = sBP[t];
    float a0 = bp, a1 = 0.f, a2 = 0.f, a3 = 0.f;
    float e0 = bp, e1 = 0.f, e2 = 0.f, e3 = 0.f;
    const float4* wr = &sW4[t * 17];
    const float4* xA = &sx4[(wid * 2) * 17];
    const float4* xB = &sx4[(wid * 2 + 1) * 17];
    #pragma unroll
    for (int k = 0; k < 16; k++) {
        float4 w  = wr[k];
        float4 xa = xA[k];
        float4 xb = xB[k];
        a0 = fmaf(xa.x, w.x, a0);  e0 = fmaf(xb.x, w.x, e0);
        a1 = fmaf(xa.y, w.y, a1);  e1 = fmaf(xb.y, w.y, e1);
        a2 = fmaf(xa.z, w.z, a2);  e2 = fmaf(xb.z, w.z, e2);
        a3 = fmaf(xa.w, w.w, a3);  e3 = fmaf(xb.w, w.w, e3);
    }
    g_zx[m0 * 32 + t]       = (a0 + a1) + (a2 + a3);
    g_zx[(m0 + 1) * 32 + t] = (e0 + e1) + (e2 + e3);
}

// ---------------------------------------------------------------------------
// Quantum head primitives (compile-time specialized).
// ---------------------------------------------------------------------------
template <int LM>
__device__ __forceinline__ void u2_lane_t(float (&ar)[8], float (&ai)[8],
                                          int lane, const float* __restrict__ u) {
    int myb = (lane & LM) ? 1 : 0;
    float dr = myb ? u[6] : u[0];
    float di = myb ? u[7] : u[1];
    float orr= myb ? u[4] : u[2];
    float oi = myb ? u[5] : u[3];
    #pragma unroll
    for (int r = 0; r < 8; r++) {
        float pr = __shfl_xor_sync(~0u, ar[r], LM);
        float pi = __shfl_xor_sync(~0u, ai[r], LM);
        float nr = dr * ar[r] - di * ai[r] + orr * pr - oi * pi;
        float ni = dr * ai[r] + di * ar[r] + orr * pi + oi * pr;
        ar[r] = nr; ai[r] = ni;
    }
}

template <int TM>
__device__ __forceinline__ void u2_reg_t(float (&ar)[8], float (&ai)[8],
                                         const float* __restrict__ u) {
    #pragma unroll
    for (int r = 0; r < 8; r++) {
        if ((r & TM) == 0) {
            const int r1 = r | TM;
            float a0r = ar[r], a0i = ai[r], a1r = ar[r1], a1i = ai[r1];
            ar[r]  = u[0]*a0r - u[1]*a0i + u[2]*a1r - u[3]*a1i;
            ai[r]  = u[0]*a0i + u[1]*a0r + u[2]*a1i + u[3]*a1r;
            ar[r1] = u[4]*a0r - u[5]*a0i + u[6]*a1r - u[7]*a1i;
            ai[r1] = u[4]*a0i + u[5]*a0r + u[6]*a1i + u[7]*a1r;
        }
    }
}

template <int P>
__device__ __forceinline__ void rz_t(float (&ar)[8], float (&ai)[8],
                                     int lane, float c, float s) {
    #pragma unroll
    for (int r = 0; r < 8; r++) {
        bool beta;
        if constexpr (P >= 3) beta = (lane >> (P - 3)) & 1;
        else                  beta = (r >> P) & 1;
        float sg = beta ? -s : s;
        float nr = fmaf(c, ar[r],  sg * ai[r]);
        float ni = fmaf(c, ai[r], -sg * ar[r]);
        ar[r] = nr; ai[r] = ni;
    }
}

template <int CM, int TM>
__device__ __forceinline__ void cnot_rr_tt(float (&ar)[8], float (&ai)[8]) {
    #pragma unroll
    for (int r = 0; r < 8; r++) {
        if (((r & CM) != 0) && ((r & TM) == 0)) {
            const int r1 = r | TM;
            float tr = ar[r]; ar[r] = ar[r1]; ar[r1] = tr;
            float ti = ai[r]; ai[r] = ai[r1]; ai[r1] = ti;
        }
    }
}

template <int TM>
__device__ __forceinline__ void cnot_lr_tt(float (&ar)[8], float (&ai)[8], int ctrl) {
    #pragma unroll
    for (int r = 0; r < 8; r++) {
        if ((r & TM) == 0) {
            const int r1 = r | TM;
            float tr = ctrl ? ar[r1] : ar[r];
            float t2 = ctrl ? ar[r]  : ar[r1];
            ar[r] = tr; ar[r1] = t2;
            float ti = ctrl ? ai[r1] : ai[r];
            float t3 = ctrl ? ai[r]  : ai[r1];
            ai[r] = ti; ai[r1] = t3;
        }
    }
}

template <int CM, int LT>
__device__ __forceinline__ void cnot_rl_tt(float (&ar)[8], float (&ai)[8]) {
    #pragma unroll
    for (int r = 0; r < 8; r++) {
        if ((r & CM) != 0) {
            float sr = __shfl_xor_sync(~0u, ar[r], LT);
            float si = __shfl_xor_sync(~0u, ai[r], LT);
            ar[r] = sr; ai[r] = si;
        }
    }
}

template <int CM, int LT>
__device__ __forceinline__ void cnot_ll_tt(float (&ar)[8], float (&ai)[8], int lane) {
    int ctrl = (lane & CM) != 0;
    #pragma unroll
    for (int r = 0; r < 8; r++) {
        float sr = __shfl_xor_sync(~0u, ar[r], LT);
        float si = __shfl_xor_sync(~0u, ai[r], LT);
        if (ctrl) { ar[r] = sr; ai[r] = si; }
    }
}

template <int TM>
__device__ __forceinline__ void rx_reg(float (&ar)[8], float (&ai)[8], float c, float s) {
    #pragma unroll
    for (int r = 0; r < 8; r++) {
        if ((r & TM) == 0) {
            const int r1 = r | TM;
            float a0r = ar[r], a0i = ai[r], a1r = ar[r1], a1i = ai[r1];
            ar[r]  = fmaf(c, a0r,  s * a1i);  ai[r]  = fmaf(c, a0i, -s * a1r);
            ar[r1] = fmaf(c, a1r,  s * a0i);  ai[r1] = fmaf(c, a1i, -s * a0r);
        }
    }
}

template <int LM>
__device__ __forceinline__ void rx_lane(float (&ar)[8], float (&ai)[8], float c, float s) {
    #pragma unroll
    for (int r = 0; r < 8; r++) {
        float pr = __shfl_xor_sync(~0u, ar[r], LM);
        float pi = __shfl_xor_sync(~0u, ai[r], LM);
        float nr = fmaf(c, ar[r],  s * pi);
        float ni = fmaf(c, ai[r], -s * pr);
        ar[r] = nr; ai[r] = ni;
    }
}

template <int O>
__device__ __forceinline__ void apply_all(float (&ar)[8], float (&ai)[8],
                                          int lane, const float* __restrict__ U) {
    if constexpr (O < EM.n) {
        constexpr int TY = EM.type[O];
        constexpr int A  = EM.a[O];
        constexpr int B  = EM.b[O];
        if constexpr (TY == 1) {
            constexpr int PC = 7 - A, PT = 7 - B;
            if constexpr (PT < 3) {
                if constexpr (PC < 3) cnot_rr_tt<(1 << PC), (1 << PT)>(ar, ai);
                else cnot_lr_tt<(1 << PT)>(ar, ai, (lane >> (PC - 3)) & 1);
            } else {
                if constexpr (PC < 3) cnot_rl_tt<(1 << PC), (1 << (PT - 3))>(ar, ai);
                else cnot_ll_tt<(1 << (PC - 3)), (1 << (PT - 3))>(ar, ai, lane);
            }
        } else if constexpr (TY == 2) {
            rz_t<7 - A>(ar, ai, lane, U[O * 8 + 0], U[O * 8 + 1]);
        } else {
            constexpr int P = 7 - A;
            if constexpr (P < 3) u2_reg_t<(1 << P)>(ar, ai, U + O * 8);
            else u2_lane_t<(1 << (P - 3))>(ar, ai, lane, U + O * 8);
        }
        apply_all<O + 1>(ar, ai, lane, U);
    }
}

__device__ __forceinline__ void head_row(
    const float* __restrict__ hsrc, int lane, float pc, float ps,
    const float* __restrict__ Whead, const float* __restrict__ b_head,
    float* __restrict__ outrow, const float* __restrict__ U)
{
    float myc = 1.f, mys = 0.f;
    if (lane < 8) __sincosf(hsrc[lane] * 0.5f, &mys, &myc);
    float lp = 1.f;
    #pragma unroll
    for (int w = 0; w < 5; w++) {
        float cw = __shfl_sync(~0u, myc, w);
        float sw = __shfl_sync(~0u, mys, w);
        lp *= ((lane >> (4 - w)) & 1) ? sw : cw;
    }
    float c5 = __shfl_sync(~0u, myc, 5), s5 = __shfl_sync(~0u, mys, 5);
    float c6 = __shfl_sync(~0u, myc, 6), s6 = __shfl_sync(~0u, mys, 6);
    float c7 = __shfl_sync(~0u, myc, 7), s7 = __shfl_sync(~0u, mys, 7);

    float ar[8], ai[8];
    #pragma unroll
    for (int r = 0; r < 8; r++) {
        ar[r] = lp * ((r & 4) ? s5 : c5) * ((r & 2) ? s6 : c6) * ((r & 1) ? s7 : c7);
        ai[r] = 0.f;
    }

    apply_all<0>(ar, ai, lane, U);

    {
        float cw, sw;
        cw = __shfl_sync(~0u, pc, 0); sw = __shfl_sync(~0u, ps, 0); rx_lane<16>(ar, ai, cw, sw);
        cw = __shfl_sync(~0u, pc, 1); sw = __shfl_sync(~0u, ps, 1); rx_lane<8>(ar, ai, cw, sw);
        cw = __shfl_sync(~0u, pc, 2); sw = __shfl_sync(~0u, ps, 2); rx_lane<4>(ar, ai, cw, sw);
        cw = __shfl_sync(~0u, pc, 3); sw = __shfl_sync(~0u, ps, 3); rx_lane<2>(ar, ai, cw, sw);
        cw = __shfl_sync(~0u, pc, 4); sw = __shfl_sync(~0u, ps, 4); rx_lane<1>(ar, ai, cw, sw);
        cw = __shfl_sync(~0u, pc, 5); sw = __shfl_sync(~0u, ps, 5); rx_reg<4>(ar, ai, cw, sw);
        cw = __shfl_sync(~0u, pc, 6); sw = __shfl_sync(~0u, ps, 6); rx_reg<2>(ar, ai, cw, sw);
        cw = __shfl_sync(~0u, pc, 7); sw = __shfl_sync(~0u, ps, 7); rx_reg<1>(ar, ai, cw, sw);
    }

    float p[8], tot = 0.f;
    #pragma unroll
    for (int r = 0; r < 8; r++) {
        p[r] = ar[r] * ar[r] + ai[r] * ai[r];
        tot += p[r];
    }
    float z5 = (p[0] + p[1] + p[2] + p[3]) - (p[4] + p[5] + p[6] + p[7]);
    float z6 = (p[0] + p[1] + p[4] + p[5]) - (p[2] + p[3] + p[6] + p[7]);
    float z7 = (p[0] + p[2] + p[4] + p[6]) - (p[1] + p[3] + p[5] + p[7]);

    float v = tot;
    #pragma unroll
    for (int mm = 1; mm < 32; mm <<= 1) {
        float tt = __shfl_xor_sync(~0u, v, mm);
        v = (lane & mm) ? (tt - v) : (tt + v);
    }
    #pragma unroll
    for (int off = 16; off; off >>= 1) {
        z5 += __shfl_xor_sync(~0u, z5, off);
        z6 += __shfl_xor_sync(~0u, z6, off);
        z7 += __shfl_xor_sync(~0u, z7, off);
    }
    float z[8];
    z[0] = __shfl_sync(~0u, v, 16);
    z[1] = __shfl_sync(~0u, v, 8);
    z[2] = __shfl_sync(~0u, v, 4);
    z[3] = __shfl_sync(~0u, v, 2);
    z[4] = __shfl_sync(~0u, v, 1);
    z[5] = z5; z[6] = z6; z[7] = z7;

    float logit = -1e30f;
    if (lane < 12) {
        logit = b_head[lane];
        #pragma unroll
        for (int k = 0; k < 8; k++) logit = fmaf(z[k], Whead[lane * 8 + k], logit);
    }
    float mx = logit;
    #pragma unroll
    for (int off = 8; off; off >>= 1) mx = fmaxf(mx, __shfl_xor_sync(~0u, mx, off, 16));
    float e = (lane < 12) ? __expf(logit - mx) : 0.f;
    float se = e;
    #pragma unroll
    for (int off = 8; off; off >>= 1) se += __shfl_xor_sync(~0u, se, off, 16);
    if (lane < 12) outrow[lane] = logit - mx - __logf(se);
}

__device__ __forceinline__ void consume_rows(
    int lane,
    const float* __restrict__ phiq, const float* __restrict__ Whead,
    const float* __restrict__ b_head, float* __restrict__ out,
    const float* __restrict__ U)
{
    float pc = 1.f, ps = 0.f;
    if (lane < 8) __sincosf(phiq[lane] * 0.5f, &ps, &pc);

    for (;;) {
        int u = 0;
        if (lane == 0) u = atomicAdd(&g_ticket, 1);
        u = __shfl_sync(~0u, u, 0);
        if (u >= NROWS) break;
        if (lane == 0) {
            while (ld_acquire(&g_flag[u]) == 0) __nanosleep(64);
        }
        __syncwarp();
        const float* hsrc = g_h + (size_t)u * H_DIM;
        int row_out = ((u & 127) << 7) + (u >> 7);
        head_row(hsrc, lane, pc, ps, Whead, b_head, out + (size_t)row_out * T_OUT, U);
    }
}

// ---------------------------------------------------------------------------
// Fused kernel, grid 1184 (8 blocks/SM, single wave).
// slot = bid%148. slot<32: scan (bid<148 only; duplicates exit).
// slot>=32: head consumers at 8 blocks/SM.
// ---------------------------------------------------------------------------
__global__ __launch_bounds__(128, 8) void fused_kernel(
    const float* __restrict__ Win, const float* __restrict__ Wout,
    const float* __restrict__ b_out,
    const float* __restrict__ phiq, const float* __restrict__ Whead,
    const float* __restrict__ b_head, float* __restrict__ out, QU P)
{
    int wid  = threadIdx.x >> 5;
    int lane = threadIdx.x & 31;
    int slot = blockIdx.x % SM_COUNT;

    if (slot < SCAN_SLOTS) {
        if (blockIdx.x >= SM_COUNT) return;   // free the scan SM's other slots

        int b = slot * 4 + wid;
        int t = lane;
        int g = t >> 3, q = t & 7;

        float wh[8], wo[8];
        #pragma unroll
        for (int j = 0; j < 8; j++) wh[j] = Win[t * 72 + 64 + j];
        #pragma unroll
        for (int j = 0; j < 8; j++) wo[j] = Wout[t * 8 + j];
        float bo = b_out[t];

        float h = 0.f, c = 0.f;
        float zn = g_zx[b * 32 + t];

        for (int s = 0; s < S_LEN; s++) {
            float z = zn;
            if (s + 1 < S_LEN) zn = g_zx[((s + 1) * B_SZ + b) * 32 + t];
            float h0 = __shfl_sync(~0u, h, 0), h1 = __shfl_sync(~0u, h, 1);
            float h2 = __shfl_sync(~0u, h, 2), h3 = __shfl_sync(~0u, h, 3);
            float h4 = __shfl_sync(~0u, h, 4), h5 = __shfl_sync(~0u, h, 5);
            float h6 = __shfl_sync(~0u, h, 6), h7 = __shfl_sync(~0u, h, 7);
            float a0 = fmaf(h0, wh[0], fmaf(h1, wh[1], fmaf(h2, wh[2], h3 * wh[3])));
            float a1 = fmaf(h4, wh[4], fmaf(h5, wh[5], fmaf(h6, wh[6], h7 * wh[7])));
            z = z + a0 + a1;

            float p = __cosf(z);
            float cj[8];
            #pragma unroll
            for (int j = 0; j < 8; j++) cj[j] = __shfl_sync(~0u, p, (g << 3) + j);
            float A = fmaf(cj[1], fmaf(cj[2], fmaf(cj[3], wo[3], wo[2]), wo[1]), wo[0]);
            float B = fmaf(cj[5], fmaf(cj[6], fmaf(cj[7], wo[7], wo[6]), wo[5]), wo[4]);
            float q01 = cj[0] * cj[1], q23 = cj[2] * cj[3];
            float Q = q01 * q23 * cj[4];
            float pre = fmaf(Q, B, fmaf(cj[0], A, bo));

            float act = (g == 2) ? fast_tanh(pre) : fast_sigmoid(pre);
            float af = __shfl_sync(~0u, act, q);
            float ii = __shfl_sync(~0u, act, 8 + q);
            float ag = __shfl_sync(~0u, act, 16 + q);
            float ao = __shfl_sync(~0u, act, 24 + q);
            c = fmaf(af, c, ii * ag);
            h = ao * fast_tanh(c);
            if (t < 8) g_h[(s * B_SZ + b) * H_DIM + t] = h;
            __syncwarp();
            if (t == 0) st_release(&g_flag[s * B_SZ + b], 1);
        }
        // scan done: help drain the head queue
        consume_rows(lane, phiq, Whead, b_head, out, P.u);
    } else {
        consume_rows(lane, phiq, Whead, b_head, out, P.u);
    }
}

// ---------------------------------------------------------------------------
// Host: numpy-legacy MT19937 (RandomState(1234)) + gate fusion -> coefficients.
// ---------------------------------------------------------------------------
namespace {
struct MTState { uint32_t mt[624]; int mti; };

static void mt_seed(MTState& s, uint32_t seed) {
    s.mt[0] = seed;
    for (int i = 1; i < 624; i++)
        s.mt[i] = 1812433253u * (s.mt[i - 1] ^ (s.mt[i - 1] >> 30)) + (uint32_t)i;
    s.mti = 624;
}
static uint32_t mt_next(MTState& s) {
    if (s.mti >= 624) {
        for (int i = 0; i < 624; i++) {
            uint32_t y = (s.mt[i] & 0x80000000u) | (s.mt[(i + 1) % 624] & 0x7fffffffu);
            s.mt[i] = s.mt[(i + 397) % 624] ^ (y >> 1) ^ ((y & 1u) ? 0x9908b0dfu : 0u);
        }
        s.mti = 0;
    }
    uint32_t y = s.mt[s.mti++];
    y ^= y >> 11;
    y ^= (y << 7) & 0x9d2c5680u;
    y ^= (y << 15) & 0xefc60000u;
    y ^= y >> 18;
    return y;
}
static uint32_t np_randint(MTState& s, uint32_t n) {
    uint32_t rng = n - 1;
    uint32_t mask = rng;
    mask |= mask >> 1; mask |= mask >> 2; mask |= mask >> 4;
    mask |= mask >> 8; mask |= mask >> 16;
    uint32_t v;
    do { v = mt_next(s) & mask; } while (v > rng);
    return v;
}
static double np_double(MTState& s) {
    uint32_t a = mt_next(s) >> 5;
    uint32_t b = mt_next(s) >> 6;
    return ((double)a * 67108864.0 + (double)b) / 9007199254740992.0;
}

typedef std::complex<double> cd;

struct Pend {
    cd m[2][2];
    int count;
    bool allrz;
    void reset() { m[0][0] = 1.0; m[0][1] = 0.0; m[1][0] = 0.0; m[1][1] = 1.0; count = 0; allrz = true; }
};

static void build_u(QU& P) {
    MTState m;
    mt_seed(m, 1234u);

    Pend pend[8];
    for (int w = 0; w < 8; w++) pend[w].reset();
    int n = 0;

    auto flush = [&](int w) {
        if (!pend[w].count) return;
        float* u = &P.u[n * 8];
        if (pend[w].allrz) {
            u[0] = (float)pend[w].m[0][0].real();
            u[1] = (float)(-pend[w].m[0][0].imag());
        } else {
            u[0] = (float)pend[w].m[0][0].real(); u[1] = (float)pend[w].m[0][0].imag();
            u[2] = (float)pend[w].m[0][1].real(); u[3] = (float)pend[w].m[0][1].imag();
            u[4] = (float)pend[w].m[1][0].real(); u[5] = (float)pend[w].m[1][0].imag();
            u[6] = (float)pend[w].m[1][1].real(); u[7] = (float)pend[w].m[1][1].imag();
        }
        n++;
        pend[w].reset();
    };

    for (int k = 0; k < N_RAW; k++) {
        uint32_t kind = np_randint(m, 4);
        if (kind == 3) {
            int c = (int)np_randint(m, 8);
            int t = (int)np_randint(m, 7);
            if (t >= c) t++;
            flush(c); flush(t);
            n++;                       // CNOT slot (no coefficients)
        } else {
            int g = (int)(kind % 3);
            int w = (int)np_randint(m, 8);
            double ang = 6.283185307179586 * np_double(m);
            double th = (double)(float)ang;
            double c = cos(th * 0.5), s = sin(th * 0.5);
            cd R[2][2];
            if (g == 0) {
                R[0][0] = c; R[0][1] = cd(0, -s);
                R[1][0] = cd(0, -s); R[1][1] = c;
            } else if (g == 1) {
                R[0][0] = c; R[0][1] = -s;
                R[1][0] = s; R[1][1] = c;
            } else {
                R[0][0] = cd(c, -s); R[0][1] = 0.0;
                R[1][0] = 0.0; R[1][1] = cd(c, s);
            }
            cd n00 = R[0][0] * pend[w].m[0][0] + R[0][1] * pend[w].m[1][0];
            cd n01 = R[0][0] * pend[w].m[0][1] + R[0][1] * pend[w].m[1][1];
            cd n10 = R[1][0] * pend[w].m[0][0] + R[1][1] * pend[w].m[1][0];
            cd n11 = R[1][0] * pend[w].m[0][1] + R[1][1] * pend[w].m[1][1];
            pend[w].m[0][0] = n00; pend[w].m[0][1] = n01;
            pend[w].m[1][0] = n10; pend[w].m[1][1] = n11;
            pend[w].count++;
            if (g != 2) pend[w].allrz = false;
        }
    }
    for (int w = 0; w < 8; w++) flush(w);
}
} // namespace

// ---------------------------------------------------------------------------
extern "C" void kernel_launch(void* const* d_in, const int* in_sizes, int n_in,
                              void* d_out, int out_size) {
    (void)in_sizes; (void)n_in; (void)out_size;
    const float* emb    = (const float*)d_in[0];
    const float* Win    = (const float*)d_in[1];
    const float* b_in   = (const float*)d_in[2];
    const float* phi    = (const float*)d_in[3];
    const float* Wout   = (const float*)d_in[4];
    const float* b_out  = (const float*)d_in[5];
    const float* phiq   = (const float*)d_in[6];
    const float* Whead  = (const float*)d_in[7];
    const float* b_head = (const float*)d_in[8];
    const int*   sent   = (const int*)d_in[9];

    QU P{};
    build_u(P);

    zx_kernel<<<NROWS / 16, 256>>>(emb, Win, b_in, phi, sent);
    fused_kernel<<<GRID_BLOCKS, 128>>>(Win, Wout, b_out, phiq, Whead, b_head,
                                       (float*)d_out, P);
}

// round 12
// speedup vs baseline: 1.2173x; 1.2173x over previous
#include <cuda_runtime.h>
#include <cstdint>
#include <math.h>
#include <complex>

// Problem constants
#define S_LEN 128
#define B_SZ  128
#define H_DIM 8
#define T_OUT 12
#define NROWS (S_LEN * B_SZ)
#define N_RAW 30
#define MAX_EMIT 40

#define SCANB 128                    // scan blocks (bids 0..127)
#define ZXB   (NROWS / 16)           // 1024 zx blocks (bids 128..1151)
#define FUSED_GRID (SCANB + ZXB)

// ---------------------------------------------------------------------------
// Device scratch
// ---------------------------------------------------------------------------
__device__ float g_zx[NROWS * 32];
__device__ float g_h[NROWS * H_DIM];
__device__ int   g_done[S_LEN];      // per-timestep zx completion counters (0..8)

struct QU { float u[MAX_EMIT * 8]; };

// ---------------------------------------------------------------------------
// Compile-time MT19937 + random-layer structure (types/wires only; no floats).
// ---------------------------------------------------------------------------
struct EmitList { int n; int type[MAX_EMIT]; int a[MAX_EMIT]; int b[MAX_EMIT]; };

constexpr uint32_t cmt_next(uint32_t (&mt)[624], int& mti) {
    if (mti >= 624) {
        for (int i = 0; i < 624; i++) {
            uint32_t y = (mt[i] & 0x80000000u) | (mt[(i + 1) % 624] & 0x7fffffffu);
            mt[i] = mt[(i + 397) % 624] ^ (y >> 1) ^ ((y & 1u) ? 0x9908b0dfu : 0u);
        }
        mti = 0;
    }
    uint32_t y = mt[mti++];
    y ^= y >> 11;
    y ^= (y << 7) & 0x9d2c5680u;
    y ^= (y << 15) & 0xefc60000u;
    y ^= y >> 18;
    return y;
}
constexpr uint32_t c_randint(uint32_t (&mt)[624], int& mti, uint32_t n) {
    uint32_t rng = n - 1;
    uint32_t mask = rng;
    mask |= mask >> 1; mask |= mask >> 2; mask |= mask >> 4;
    mask |= mask >> 8; mask |= mask >> 16;
    uint32_t v = cmt_next(mt, mti) & mask;
    while (v > rng) v = cmt_next(mt, mti) & mask;
    return v;
}

constexpr EmitList compute_emitted() {
    uint32_t mt[624] = {};
    mt[0] = 1234u;
    for (int i = 1; i < 624; i++)
        mt[i] = 1812433253u * (mt[i - 1] ^ (mt[i - 1] >> 30)) + (uint32_t)i;
    int mti = 624;

    EmitList E{};
    int cnt[8] = {};
    bool allrz[8] = {true, true, true, true, true, true, true, true};

    for (int k = 0; k < N_RAW; k++) {
        uint32_t kind = c_randint(mt, mti, 4);
        if (kind == 3) {
            int c = (int)c_randint(mt, mti, 8);
            int t = (int)c_randint(mt, mti, 7);
            if (t >= c) t++;
            if (cnt[c]) { E.type[E.n] = allrz[c] ? 2 : 0; E.a[E.n] = c; E.b[E.n] = 0; E.n++; cnt[c] = 0; allrz[c] = true; }
            if (cnt[t]) { E.type[E.n] = allrz[t] ? 2 : 0; E.a[E.n] = t; E.b[E.n] = 0; E.n++; cnt[t] = 0; allrz[t] = true; }
            E.type[E.n] = 1; E.a[E.n] = c; E.b[E.n] = t; E.n++;
        } else {
            int g = (int)(kind % 3);
            int w = (int)c_randint(mt, mti, 8);
            cmt_next(mt, mti); cmt_next(mt, mti);   // uniform() draws
            cnt[w]++;
            if (g != 2) allrz[w] = false;
        }
    }
    for (int w = 0; w < 8; w++)
        if (cnt[w]) { E.type[E.n] = allrz[w] ? 2 : 0; E.a[E.n] = w; E.b[E.n] = 0; E.n++; }
    return E;
}

constexpr EmitList EM = compute_emitted();

// ---------------------------------------------------------------------------
// Fast helpers
// ---------------------------------------------------------------------------
__device__ __forceinline__ float fast_rcp(float x){ float r; asm("rcp.approx.f32 %0,%1;":"=f"(r):"f"(x)); return r; }
__device__ __forceinline__ float fast_ex2(float x){ float r; asm("ex2.approx.f32 %0,%1;":"=f"(r):"f"(x)); return r; }
__device__ __forceinline__ float fast_exp(float x){ return fast_ex2(x * 1.4426950408889634f); }
__device__ __forceinline__ float fast_sigmoid(float x){ return fast_rcp(1.f + fast_exp(-x)); }
__device__ __forceinline__ float fast_tanh(float x){
    x = fminf(fmaxf(x, -9.f), 9.f);
    float e = fast_exp(2.f * x);
    return (e - 1.f) * fast_rcp(e + 1.f);
}
__device__ __forceinline__ int ld_acquire(const int* p){
    int v; asm volatile("ld.acquire.gpu.global.b32 %0,[%1];":"=r"(v):"l"(p):"memory"); return v;
}

// ---------------------------------------------------------------------------
// Fused kernel 1: scan blocks [0,128) + zx blocks [128,1152).
// zx body identical to R10; publishes per-timestep completion via g_done[s].
// Scan consumes timesteps as they become ready (prefix pointer rdy).
// ---------------------------------------------------------------------------
__global__ __launch_bounds__(256) void fused_zx_scan(
    const float* __restrict__ emb, const float* __restrict__ Win,
    const float* __restrict__ b_in, const float* __restrict__ phi,
    const int* __restrict__ sent32,
    const float* __restrict__ Wout, const float* __restrict__ b_out)
{
    if (blockIdx.x < SCANB) {
        // ----------------- scan chain b = blockIdx.x (warp 0 only) ---------
        if (threadIdx.x >= 32) return;
        int b = blockIdx.x;
        int t = threadIdx.x;
        int g = t >> 3, q = t & 7;

        float wh[8], wo[8];
        #pragma unroll
        for (int j = 0; j < 8; j++) wh[j] = Win[t * 72 + 64 + j];
        #pragma unroll
        for (int j = 0; j < 8; j++) wo[j] = Wout[t * 8 + j];
        float bo = b_out[t];

        float h = 0.f, c = 0.f;
        float zn = 0.f;
        bool have = false;
        int rdy = 0;                          // g_done[0..rdy) known == 8

        for (int s = 0; s < S_LEN; s++) {
            float z;
            if (have) {
                z = zn;
            } else {
                while (rdy <= s) {
                    int v = ld_acquire(&g_done[rdy]);
                    if (v == 8) rdy++; else __nanosleep(64);
                }
                z = g_zx[(s * B_SZ + b) * 32 + t];
            }
            // issue up to 2 readiness probes; results consumed after compute
            int p0 = 0, p1 = 0;
            bool need = (rdy < S_LEN);
            if (need) {
                p0 = ld_acquire(&g_done[rdy]);
                p1 = (rdy + 1 < S_LEN) ? ld_acquire(&g_done[rdy + 1]) : 0;
            }

            float h0 = __shfl_sync(~0u, h, 0), h1 = __shfl_sync(~0u, h, 1);
            float h2 = __shfl_sync(~0u, h, 2), h3 = __shfl_sync(~0u, h, 3);
            float h4 = __shfl_sync(~0u, h, 4), h5 = __shfl_sync(~0u, h, 5);
            float h6 = __shfl_sync(~0u, h, 6), h7 = __shfl_sync(~0u, h, 7);
            float a0 = fmaf(h0, wh[0], fmaf(h1, wh[1], fmaf(h2, wh[2], h3 * wh[3])));
            float a1 = fmaf(h4, wh[4], fmaf(h5, wh[5], fmaf(h6, wh[6], h7 * wh[7])));
            z = z + a0 + a1;

            float p = __cosf(z);
            float cj[8];
            #pragma unroll
            for (int j = 0; j < 8; j++) cj[j] = __shfl_sync(~0u, p, (g << 3) + j);
            float A = fmaf(cj[1], fmaf(cj[2], fmaf(cj[3], wo[3], wo[2]), wo[1]), wo[0]);
            float B = fmaf(cj[5], fmaf(cj[6], fmaf(cj[7], wo[7], wo[6]), wo[5]), wo[4]);
            float q01 = cj[0] * cj[1], q23 = cj[2] * cj[3];
            float Q = q01 * q23 * cj[4];
            float pre = fmaf(Q, B, fmaf(cj[0], A, bo));

            float act = (g == 2) ? fast_tanh(pre) : fast_sigmoid(pre);
            float af = __shfl_sync(~0u, act, q);
            float ii = __shfl_sync(~0u, act, 8 + q);
            float ag = __shfl_sync(~0u, act, 16 + q);
            float ao = __shfl_sync(~0u, act, 24 + q);
            c = fmaf(af, c, ii * ag);
            h = ao * fast_tanh(c);
            if (t < 8) g_h[(s * B_SZ + b) * H_DIM + t] = h;

            // consume probes, then prefetch next z if proven ready
            if (need && p0 == 8) { rdy++; if (p1 == 8) rdy++; }
            have = false;
            if (s + 1 < S_LEN && rdy > s + 1) {
                zn = g_zx[((s + 1) * B_SZ + b) * 32 + t];
                have = true;
            }
        }
    } else {
        // ----------------- zx producer block (R10 body) --------------------
        __shared__ float4 sW4[32 * 17];
        __shared__ float4 sx4[16 * 17];
        __shared__ float  sBP[32];
        __shared__ int    sIs64;

        int tid = threadIdx.x, lane = tid & 31, wid = tid >> 5;
        int zb = blockIdx.x - SCANB;

        if (wid == 0) {
            int acc = sent32[2 * lane + 1] | sent32[2 * (lane + 32) + 1];
            #pragma unroll
            for (int off = 16; off; off >>= 1) acc |= __shfl_xor_sync(~0u, acc, off);
            if (lane == 0) sIs64 = (acc == 0) ? 1 : 0;
        }
        for (int i = tid; i < 512; i += 256) {
            int t = i >> 4, k = i & 15;
            sW4[t * 17 + k] = ((const float4*)(Win + t * 72))[k];
        }
        if (tid < 32) sBP[tid] = b_in[tid] + phi[tid];
        __syncthreads();

        int m0 = zb * 16 + wid * 2;
        int half = lane >> 4;
        int m = m0 + half;
        int tok = sIs64 ? sent32[2 * m] : sent32[m];
        sx4[(wid * 2 + half) * 17 + (lane & 15)] =
            ((const float4*)(emb + (size_t)tok * 64))[lane & 15];
        __syncwarp();

        int t = lane;
        float bp = sBP[t];
        float a0 = bp, a1 = 0.f, a2 = 0.f, a3 = 0.f;
        float e0 = bp, e1 = 0.f, e2 = 0.f, e3 = 0.f;
        const float4* wr = &sW4[t * 17];
        const float4* xA = &sx4[(wid * 2) * 17];
        const float4* xB = &sx4[(wid * 2 + 1) * 17];
        #pragma unroll
        for (int k = 0; k < 16; k++) {
            float4 w  = wr[k];
            float4 xa = xA[k];
            float4 xb = xB[k];
            a0 = fmaf(xa.x, w.x, a0);  e0 = fmaf(xb.x, w.x, e0);
            a1 = fmaf(xa.y, w.y, a1);  e1 = fmaf(xb.y, w.y, e1);
            a2 = fmaf(xa.z, w.z, a2);  e2 = fmaf(xb.z, w.z, e2);
            a3 = fmaf(xa.w, w.w, a3);  e3 = fmaf(xb.w, w.w, e3);
        }
        g_zx[m0 * 32 + t]       = (a0 + a1) + (a2 + a3);
        g_zx[(m0 + 1) * 32 + t] = (e0 + e1) + (e2 + e3);

        // publish completion of this block's 16 rows (all belong to s = zb/8)
        __threadfence();
        __syncthreads();
        if (tid == 0) atomicAdd(&g_done[(zb * 16) >> 7], 1);
    }
}

// ---------------------------------------------------------------------------
// Quantum head primitives (compile-time specialized).
// ---------------------------------------------------------------------------
template <int LM>
__device__ __forceinline__ void u2_lane_t(float (&ar)[8], float (&ai)[8],
                                          int lane, const float* __restrict__ u) {
    int myb = (lane & LM) ? 1 : 0;
    float dr = myb ? u[6] : u[0];
    float di = myb ? u[7] : u[1];
    float orr= myb ? u[4] : u[2];
    float oi = myb ? u[5] : u[3];
    #pragma unroll
    for (int r = 0; r < 8; r++) {
        float pr = __shfl_xor_sync(~0u, ar[r], LM);
        float pi = __shfl_xor_sync(~0u, ai[r], LM);
        float nr = dr * ar[r] - di * ai[r] + orr * pr - oi * pi;
        float ni = dr * ai[r] + di * ar[r] + orr * pi + oi * pr;
        ar[r] = nr; ai[r] = ni;
    }
}

template <int TM>
__device__ __forceinline__ void u2_reg_t(float (&ar)[8], float (&ai)[8],
                                         const float* __restrict__ u) {
    #pragma unroll
    for (int r = 0; r < 8; r++) {
        if ((r & TM) == 0) {
            const int r1 = r | TM;
            float a0r = ar[r], a0i = ai[r], a1r = ar[r1], a1i = ai[r1];
            ar[r]  = u[0]*a0r - u[1]*a0i + u[2]*a1r - u[3]*a1i;
            ai[r]  = u[0]*a0i + u[1]*a0r + u[2]*a1i + u[3]*a1r;
            ar[r1] = u[4]*a0r - u[5]*a0i + u[6]*a1r - u[7]*a1i;
            ai[r1] = u[4]*a0i + u[5]*a0r + u[6]*a1i + u[7]*a1r;
        }
    }
}

template <int P>
__device__ __forceinline__ void rz_t(float (&ar)[8], float (&ai)[8],
                                     int lane, float c, float s) {
    #pragma unroll
    for (int r = 0; r < 8; r++) {
        bool beta;
        if constexpr (P >= 3) beta = (lane >> (P - 3)) & 1;
        else                  beta = (r >> P) & 1;
        float sg = beta ? -s : s;
        float nr = fmaf(c, ar[r],  sg * ai[r]);
        float ni = fmaf(c, ai[r], -sg * ar[r]);
        ar[r] = nr; ai[r] = ni;
    }
}

template <int CM, int TM>
__device__ __forceinline__ void cnot_rr_tt(float (&ar)[8], float (&ai)[8]) {
    #pragma unroll
    for (int r = 0; r < 8; r++) {
        if (((r & CM) != 0) && ((r & TM) == 0)) {
            const int r1 = r | TM;
            float tr = ar[r]; ar[r] = ar[r1]; ar[r1] = tr;
            float ti = ai[r]; ai[r] = ai[r1]; ai[r1] = ti;
        }
    }
}

template <int TM>
__device__ __forceinline__ void cnot_lr_tt(float (&ar)[8], float (&ai)[8], int ctrl) {
    #pragma unroll
    for (int r = 0; r < 8; r++) {
        if ((r & TM) == 0) {
            const int r1 = r | TM;
            float tr = ctrl ? ar[r1] : ar[r];
            float t2 = ctrl ? ar[r]  : ar[r1];
            ar[r] = tr; ar[r1] = t2;
            float ti = ctrl ? ai[r1] : ai[r];
            float t3 = ctrl ? ai[r]  : ai[r1];
            ai[r] = ti; ai[r1] = t3;
        }
    }
}

template <int CM, int LT>
__device__ __forceinline__ void cnot_rl_tt(float (&ar)[8], float (&ai)[8]) {
    #pragma unroll
    for (int r = 0; r < 8; r++) {
        if ((r & CM) != 0) {
            float sr = __shfl_xor_sync(~0u, ar[r], LT);
            float si = __shfl_xor_sync(~0u, ai[r], LT);
            ar[r] = sr; ai[r] = si;
        }
    }
}

template <int CM, int LT>
__device__ __forceinline__ void cnot_ll_tt(float (&ar)[8], float (&ai)[8], int lane) {
    int ctrl = (lane & CM) != 0;
    #pragma unroll
    for (int r = 0; r < 8; r++) {
        float sr = __shfl_xor_sync(~0u, ar[r], LT);
        float si = __shfl_xor_sync(~0u, ai[r], LT);
        if (ctrl) { ar[r] = sr; ai[r] = si; }
    }
}

template <int TM>
__device__ __forceinline__ void rx_reg(float (&ar)[8], float (&ai)[8], float c, float s) {
    #pragma unroll
    for (int r = 0; r < 8; r++) {
        if ((r & TM) == 0) {
            const int r1 = r | TM;
            float a0r = ar[r], a0i = ai[r], a1r = ar[r1], a1i = ai[r1];
            ar[r]  = fmaf(c, a0r,  s * a1i);  ai[r]  = fmaf(c, a0i, -s * a1r);
            ar[r1] = fmaf(c, a1r,  s * a0i);  ai[r1] = fmaf(c, a1i, -s * a0r);
        }
    }
}

template <int LM>
__device__ __forceinline__ void rx_lane(float (&ar)[8], float (&ai)[8], float c, float s) {
    #pragma unroll
    for (int r = 0; r < 8; r++) {
        float pr = __shfl_xor_sync(~0u, ar[r], LM);
        float pi = __shfl_xor_sync(~0u, ai[r], LM);
        float nr = fmaf(c, ar[r],  s * pi);
        float ni = fmaf(c, ai[r], -s * pr);
        ar[r] = nr; ai[r] = ni;
    }
}

template <int O>
__device__ __forceinline__ void apply_all(float (&ar)[8], float (&ai)[8],
                                          int lane, const float* __restrict__ U) {
    if constexpr (O < EM.n) {
        constexpr int TY = EM.type[O];
        constexpr int A  = EM.a[O];
        constexpr int B  = EM.b[O];
        if constexpr (TY == 1) {
            constexpr int PC = 7 - A, PT = 7 - B;
            if constexpr (PT < 3) {
                if constexpr (PC < 3) cnot_rr_tt<(1 << PC), (1 << PT)>(ar, ai);
                else cnot_lr_tt<(1 << PT)>(ar, ai, (lane >> (PC - 3)) & 1);
            } else {
                if constexpr (PC < 3) cnot_rl_tt<(1 << PC), (1 << (PT - 3))>(ar, ai);
                else cnot_ll_tt<(1 << (PC - 3)), (1 << (PT - 3))>(ar, ai, lane);
            }
        } else if constexpr (TY == 2) {
            rz_t<7 - A>(ar, ai, lane, U[O * 8 + 0], U[O * 8 + 1]);
        } else {
            constexpr int P = 7 - A;
            if constexpr (P < 3) u2_reg_t<(1 << P)>(ar, ai, U + O * 8);
            else u2_lane_t<(1 << (P - 3))>(ar, ai, lane, U + O * 8);
        }
        apply_all<O + 1>(ar, ai, lane, U);
    }
}

// ---------------------------------------------------------------------------
// Kernel 2: quantum head + log-softmax. One warp per output row.
// Block 0 also resets g_done for the NEXT launch (fused kernel of this
// launch has already fully consumed it — kernel boundary ordering).
// ---------------------------------------------------------------------------
__global__ __launch_bounds__(128) void head_kernel(
    const float* __restrict__ phiq, const float* __restrict__ Whead,
    const float* __restrict__ b_head, float* __restrict__ out, QU P)
{
    if (blockIdx.x == 0 && threadIdx.x < S_LEN) g_done[threadIdx.x] = 0;

    int warp = (blockIdx.x * blockDim.x + threadIdx.x) >> 5;
    int lane = threadIdx.x & 31;
    int s_out = warp >> 7, b_out = warp & 127;
    const float* hsrc = g_h + ((b_out << 7) + s_out) * H_DIM;

    float myc = 1.f, mys = 0.f;
    if (lane < 8) __sincosf(hsrc[lane] * 0.5f, &mys, &myc);
    float lp = 1.f;
    #pragma unroll
    for (int w = 0; w < 5; w++) {
        float cw = __shfl_sync(~0u, myc, w);
        float sw = __shfl_sync(~0u, mys, w);
        lp *= ((lane >> (4 - w)) & 1) ? sw : cw;
    }
    float c5 = __shfl_sync(~0u, myc, 5), s5 = __shfl_sync(~0u, mys, 5);
    float c6 = __shfl_sync(~0u, myc, 6), s6 = __shfl_sync(~0u, mys, 6);
    float c7 = __shfl_sync(~0u, myc, 7), s7 = __shfl_sync(~0u, mys, 7);

    float ar[8], ai[8];
    #pragma unroll
    for (int r = 0; r < 8; r++) {
        ar[r] = lp * ((r & 4) ? s5 : c5) * ((r & 2) ? s6 : c6) * ((r & 1) ? s7 : c7);
        ai[r] = 0.f;
    }

    apply_all<0>(ar, ai, lane, P.u);

    float pc = 1.f, ps = 0.f;
    if (lane < 8) __sincosf(phiq[lane] * 0.5f, &ps, &pc);
    {
        float cw, sw;
        cw = __shfl_sync(~0u, pc, 0); sw = __shfl_sync(~0u, ps, 0); rx_lane<16>(ar, ai, cw, sw);
        cw = __shfl_sync(~0u, pc, 1); sw = __shfl_sync(~0u, ps, 1); rx_lane<8>(ar, ai, cw, sw);
        cw = __shfl_sync(~0u, pc, 2); sw = __shfl_sync(~0u, ps, 2); rx_lane<4>(ar, ai, cw, sw);
        cw = __shfl_sync(~0u, pc, 3); sw = __shfl_sync(~0u, ps, 3); rx_lane<2>(ar, ai, cw, sw);
        cw = __shfl_sync(~0u, pc, 4); sw = __shfl_sync(~0u, ps, 4); rx_lane<1>(ar, ai, cw, sw);
        cw = __shfl_sync(~0u, pc, 5); sw = __shfl_sync(~0u, ps, 5); rx_reg<4>(ar, ai, cw, sw);
        cw = __shfl_sync(~0u, pc, 6); sw = __shfl_sync(~0u, ps, 6); rx_reg<2>(ar, ai, cw, sw);
        cw = __shfl_sync(~0u, pc, 7); sw = __shfl_sync(~0u, ps, 7); rx_reg<1>(ar, ai, cw, sw);
    }

    float p[8], tot = 0.f;
    #pragma unroll
    for (int r = 0; r < 8; r++) {
        p[r] = ar[r] * ar[r] + ai[r] * ai[r];
        tot += p[r];
    }
    float z5 = (p[0] + p[1] + p[2] + p[3]) - (p[4] + p[5] + p[6] + p[7]);
    float z6 = (p[0] + p[1] + p[4] + p[5]) - (p[2] + p[3] + p[6] + p[7]);
    float z7 = (p[0] + p[2] + p[4] + p[6]) - (p[1] + p[3] + p[5] + p[7]);

    float v = tot;
    #pragma unroll
    for (int mm = 1; mm < 32; mm <<= 1) {
        float tt = __shfl_xor_sync(~0u, v, mm);
        v = (lane & mm) ? (tt - v) : (tt + v);
    }
    #pragma unroll
    for (int off = 16; off; off >>= 1) {
        z5 += __shfl_xor_sync(~0u, z5, off);
        z6 += __shfl_xor_sync(~0u, z6, off);
        z7 += __shfl_xor_sync(~0u, z7, off);
    }
    float z[8];
    z[0] = __shfl_sync(~0u, v, 16);
    z[1] = __shfl_sync(~0u, v, 8);
    z[2] = __shfl_sync(~0u, v, 4);
    z[3] = __shfl_sync(~0u, v, 2);
    z[4] = __shfl_sync(~0u, v, 1);
    z[5] = z5; z[6] = z6; z[7] = z7;

    float logit = -1e30f;
    if (lane < 12) {
        logit = b_head[lane];
        #pragma unroll
        for (int k = 0; k < 8; k++) logit = fmaf(z[k], Whead[lane * 8 + k], logit);
    }
    float mx = logit;
    #pragma unroll
    for (int off = 8; off; off >>= 1) mx = fmaxf(mx, __shfl_xor_sync(~0u, mx, off, 16));
    float e = (lane < 12) ? __expf(logit - mx) : 0.f;
    float se = e;
    #pragma unroll
    for (int off = 8; off; off >>= 1) se += __shfl_xor_sync(~0u, se, off, 16);
    if (lane < 12) out[warp * T_OUT + lane] = logit - mx - __logf(se);
}

// ---------------------------------------------------------------------------
// Host: numpy-legacy MT19937 (RandomState(1234)) + gate fusion -> coefficients.
// ---------------------------------------------------------------------------
namespace {
struct MTState { uint32_t mt[624]; int mti; };

static void mt_seed(MTState& s, uint32_t seed) {
    s.mt[0] = seed;
    for (int i = 1; i < 624; i++)
        s.mt[i] = 1812433253u * (s.mt[i - 1] ^ (s.mt[i - 1] >> 30)) + (uint32_t)i;
    s.mti = 624;
}
static uint32_t mt_next(MTState& s) {
    if (s.mti >= 624) {
        for (int i = 0; i < 624; i++) {
            uint32_t y = (s.mt[i] & 0x80000000u) | (s.mt[(i + 1) % 624] & 0x7fffffffu);
            s.mt[i] = s.mt[(i + 397) % 624] ^ (y >> 1) ^ ((y & 1u) ? 0x9908b0dfu : 0u);
        }
        s.mti = 0;
    }
    uint32_t y = s.mt[s.mti++];
    y ^= y >> 11;
    y ^= (y << 7) & 0x9d2c5680u;
    y ^= (y << 15) & 0xefc60000u;
    y ^= y >> 18;
    return y;
}
static uint32_t np_randint(MTState& s, uint32_t n) {
    uint32_t rng = n - 1;
    uint32_t mask = rng;
    mask |= mask >> 1; mask |= mask >> 2; mask |= mask >> 4;
    mask |= mask >> 8; mask |= mask >> 16;
    uint32_t v;
    do { v = mt_next(s) & mask; } while (v > rng);
    return v;
}
static double np_double(MTState& s) {
    uint32_t a = mt_next(s) >> 5;
    uint32_t b = mt_next(s) >> 6;
    return ((double)a * 67108864.0 + (double)b) / 9007199254740992.0;
}

typedef std::complex<double> cd;

struct Pend {
    cd m[2][2];
    int count;
    bool allrz;
    void reset() { m[0][0] = 1.0; m[0][1] = 0.0; m[1][0] = 0.0; m[1][1] = 1.0; count = 0; allrz = true; }
};

static void build_u(QU& P) {
    MTState m;
    mt_seed(m, 1234u);

    Pend pend[8];
    for (int w = 0; w < 8; w++) pend[w].reset();
    int n = 0;

    auto flush = [&](int w) {
        if (!pend[w].count) return;
        float* u = &P.u[n * 8];
        if (pend[w].allrz) {
            u[0] = (float)pend[w].m[0][0].real();
            u[1] = (float)(-pend[w].m[0][0].imag());
        } else {
            u[0] = (float)pend[w].m[0][0].real(); u[1] = (float)pend[w].m[0][0].imag();
            u[2] = (float)pend[w].m[0][1].real(); u[3] = (float)pend[w].m[0][1].imag();
            u[4] = (float)pend[w].m[1][0].real(); u[5] = (float)pend[w].m[1][0].imag();
            u[6] = (float)pend[w].m[1][1].real(); u[7] = (float)pend[w].m[1][1].imag();
        }
        n++;
        pend[w].reset();
    };

    for (int k = 0; k < N_RAW; k++) {
        uint32_t kind = np_randint(m, 4);
        if (kind == 3) {
            int c = (int)np_randint(m, 8);
            int t = (int)np_randint(m, 7);
            if (t >= c) t++;
            flush(c); flush(t);
            n++;                       // CNOT slot (no coefficients)
        } else {
            int g = (int)(kind % 3);
            int w = (int)np_randint(m, 8);
            double ang = 6.283185307179586 * np_double(m);
            double th = (double)(float)ang;
            double c = cos(th * 0.5), s = sin(th * 0.5);
            cd R[2][2];
            if (g == 0) {
                R[0][0] = c; R[0][1] = cd(0, -s);
                R[1][0] = cd(0, -s); R[1][1] = c;
            } else if (g == 1) {
                R[0][0] = c; R[0][1] = -s;
                R[1][0] = s; R[1][1] = c;
            } else {
                R[0][0] = cd(c, -s); R[0][1] = 0.0;
                R[1][0] = 0.0; R[1][1] = cd(c, s);
            }
            cd n00 = R[0][0] * pend[w].m[0][0] + R[0][1] * pend[w].m[1][0];
            cd n01 = R[0][0] * pend[w].m[0][1] + R[0][1] * pend[w].m[1][1];
            cd n10 = R[1][0] * pend[w].m[0][0] + R[1][1] * pend[w].m[1][0];
            cd n11 = R[1][0] * pend[w].m[0][1] + R[1][1] * pend[w].m[1][1];
            pend[w].m[0][0] = n00; pend[w].m[0][1] = n01;
            pend[w].m[1][0] = n10; pend[w].m[1][1] = n11;
            pend[w].count++;
            if (g != 2) pend[w].allrz = false;
        }
    }
    for (int w = 0; w < 8; w++) flush(w);
}
} // namespace

// ---------------------------------------------------------------------------
extern "C" void kernel_launch(void* const* d_in, const int* in_sizes, int n_in,
                              void* d_out, int out_size) {
    (void)in_sizes; (void)n_in; (void)out_size;
    const float* emb    = (const float*)d_in[0];
    const float* Win    = (const float*)d_in[1];
    const float* b_in   = (const float*)d_in[2];
    const float* phi    = (const float*)d_in[3];
    const float* Wout   = (const float*)d_in[4];
    const float* b_out  = (const float*)d_in[5];
    const float* phiq   = (const float*)d_in[6];
    const float* Whead  = (const float*)d_in[7];
    const float* b_head = (const float*)d_in[8];
    const int*   sent   = (const int*)d_in[9];

    QU P{};
    build_u(P);

    fused_zx_scan<<<FUSED_GRID, 256>>>(emb, Win, b_in, phi, sent, Wout, b_out);
    head_kernel<<<NROWS / 4, 128>>>(phiq, Whead, b_head, (float*)d_out, P);
}

// round 13
// speedup vs baseline: 1.9806x; 1.6270x over previous
#include <cuda_runtime.h>
#include <cstdint>
#include <math.h>
#include <complex>

// Problem constants
#define S_LEN 128
#define B_SZ  128
#define H_DIM 8
#define T_OUT 12
#define NROWS (S_LEN * B_SZ)
#define N_RAW 30
#define MAX_EMIT 40

// ---------------------------------------------------------------------------
// Device scratch
// ---------------------------------------------------------------------------
__device__ float g_zx[NROWS * 32];
__device__ float g_h[NROWS * H_DIM];

struct QU { float u[MAX_EMIT * 8]; };   // fused-op coefficients, host-computed

// ---------------------------------------------------------------------------
// Compile-time MT19937 + random-layer structure (types/wires only; no floats).
// ---------------------------------------------------------------------------
struct EmitList { int n; int type[MAX_EMIT]; int a[MAX_EMIT]; int b[MAX_EMIT]; };

constexpr uint32_t cmt_next(uint32_t (&mt)[624], int& mti) {
    if (mti >= 624) {
        for (int i = 0; i < 624; i++) {
            uint32_t y = (mt[i] & 0x80000000u) | (mt[(i + 1) % 624] & 0x7fffffffu);
            mt[i] = mt[(i + 397) % 624] ^ (y >> 1) ^ ((y & 1u) ? 0x9908b0dfu : 0u);
        }
        mti = 0;
    }
    uint32_t y = mt[mti++];
    y ^= y >> 11;
    y ^= (y << 7) & 0x9d2c5680u;
    y ^= (y << 15) & 0xefc60000u;
    y ^= y >> 18;
    return y;
}
constexpr uint32_t c_randint(uint32_t (&mt)[624], int& mti, uint32_t n) {
    uint32_t rng = n - 1;
    uint32_t mask = rng;
    mask |= mask >> 1; mask |= mask >> 2; mask |= mask >> 4;
    mask |= mask >> 8; mask |= mask >> 16;
    uint32_t v = cmt_next(mt, mti) & mask;
    while (v > rng) v = cmt_next(mt, mti) & mask;
    return v;
}

constexpr EmitList compute_emitted() {
    uint32_t mt[624] = {};
    mt[0] = 1234u;
    for (int i = 1; i < 624; i++)
        mt[i] = 1812433253u * (mt[i - 1] ^ (mt[i - 1] >> 30)) + (uint32_t)i;
    int mti = 624;

    EmitList E{};
    int cnt[8] = {};
    bool allrz[8] = {true, true, true, true, true, true, true, true};

    for (int k = 0; k < N_RAW; k++) {
        uint32_t kind = c_randint(mt, mti, 4);
        if (kind == 3) {
            int c = (int)c_randint(mt, mti, 8);
            int t = (int)c_randint(mt, mti, 7);
            if (t >= c) t++;
            if (cnt[c]) { E.type[E.n] = allrz[c] ? 2 : 0; E.a[E.n] = c; E.b[E.n] = 0; E.n++; cnt[c] = 0; allrz[c] = true; }
            if (cnt[t]) { E.type[E.n] = allrz[t] ? 2 : 0; E.a[E.n] = t; E.b[E.n] = 0; E.n++; cnt[t] = 0; allrz[t] = true; }
            E.type[E.n] = 1; E.a[E.n] = c; E.b[E.n] = t; E.n++;
        } else {
            int g = (int)(kind % 3);
            int w = (int)c_randint(mt, mti, 8);
            cmt_next(mt, mti); cmt_next(mt, mti);   // uniform() draws
            cnt[w]++;
            if (g != 2) allrz[w] = false;
        }
    }
    for (int w = 0; w < 8; w++)
        if (cnt[w]) { E.type[E.n] = allrz[w] ? 2 : 0; E.a[E.n] = w; E.b[E.n] = 0; E.n++; }
    return E;
}

constexpr EmitList EM = compute_emitted();

// ---------------------------------------------------------------------------
// Fast helpers
// ---------------------------------------------------------------------------
__device__ __forceinline__ float fast_rcp(float x){ float r; asm("rcp.approx.f32 %0,%1;":"=f"(r):"f"(x)); return r; }
__device__ __forceinline__ float fast_ex2(float x){ float r; asm("ex2.approx.f32 %0,%1;":"=f"(r):"f"(x)); return r; }
__device__ __forceinline__ float fast_exp(float x){ return fast_ex2(x * 1.4426950408889634f); }
__device__ __forceinline__ float fast_sigmoid(float x){ return fast_rcp(1.f + fast_exp(-x)); }
__device__ __forceinline__ float fast_tanh(float x){
    x = fminf(fmaxf(x, -9.f), 9.f);
    float e = fast_exp(2.f * x);
    return (e - 1.f) * fast_rcp(e + 1.f);
}

// ---------------------------------------------------------------------------
// Kernel 1: zx[s][b][t] = emb[tok]·Win[t][0:64] + b_in[t] + phi[t]
// 256 threads, 32 rows per block, FOUR rows per warp (MLP=4).
// Staging: row r (0..3) staged by lanes [r*8, r*8+8), 2 float4 each.
// ---------------------------------------------------------------------------
__global__ __launch_bounds__(256) void zx_kernel(
    const float* __restrict__ emb, const float* __restrict__ Win,
    const float* __restrict__ b_in, const float* __restrict__ phi,
    const int* __restrict__ sent32)
{
    __shared__ float4 sW4[32 * 17];    // W[t] as 16 float4, padded stride 17
    __shared__ float4 sx4[32 * 17];    // 32 staged x rows
    __shared__ float  sBP[32];
    __shared__ int    sIs64;

    int tid = threadIdx.x, lane = tid & 31, wid = tid >> 5;

    if (wid == 0) {
        int acc = sent32[2 * lane + 1] | sent32[2 * (lane + 32) + 1];
        #pragma unroll
        for (int off = 16; off; off >>= 1) acc |= __shfl_xor_sync(~0u, acc, off);
        if (lane == 0) sIs64 = (acc == 0) ? 1 : 0;
    }
    for (int i = tid; i < 512; i += 256) {
        int t = i >> 4, k = i & 15;
        sW4[t * 17 + k] = ((const float4*)(Win + t * 72))[k];
    }
    if (tid < 32) sBP[tid] = b_in[tid] + phi[tid];
    __syncthreads();

    int m0 = blockIdx.x * 32 + wid * 4;      // rows m0 .. m0+3
    int r = lane >> 3;                        // row index 0..3
    int kk = lane & 7;                        // float4 pair index
    int m = m0 + r;
    int tok = sIs64 ? sent32[2 * m] : sent32[m];
    const float4* xsrc = (const float4*)(emb + (size_t)tok * 64);
    // two independent loads per lane -> 2 outstanding per chain, 4 chains/warp
    float4 v0 = xsrc[kk];
    float4 v1 = xsrc[kk + 8];
    sx4[(wid * 4 + r) * 17 + kk]     = v0;
    sx4[(wid * 4 + r) * 17 + kk + 8] = v1;
    __syncwarp();

    int t = lane;
    float bp = sBP[t];
    float a0[4], a1[4], a2[4], a3[4];
    #pragma unroll
    for (int j = 0; j < 4; j++) { a0[j] = (j == 0) ? bp : bp; a1[j] = 0.f; a2[j] = 0.f; a3[j] = 0.f; }
    // note: a0[j] starts at bp for each row j (bias added once per row)
    #pragma unroll
    for (int j = 1; j < 4; j++) a0[j] = bp;

    const float4* wr = &sW4[t * 17];
    const float4* x0 = &sx4[(wid * 4 + 0) * 17];
    const float4* x1 = &sx4[(wid * 4 + 1) * 17];
    const float4* x2 = &sx4[(wid * 4 + 2) * 17];
    const float4* x3 = &sx4[(wid * 4 + 3) * 17];
    #pragma unroll
    for (int k = 0; k < 16; k++) {
        float4 w  = wr[k];
        float4 b0 = x0[k], b1 = x1[k], b2 = x2[k], b3 = x3[k];  // broadcasts
        a0[0] = fmaf(b0.x, w.x, a0[0]); a1[0] = fmaf(b0.y, w.y, a1[0]);
        a2[0] = fmaf(b0.z, w.z, a2[0]); a3[0] = fmaf(b0.w, w.w, a3[0]);
        a0[1] = fmaf(b1.x, w.x, a0[1]); a1[1] = fmaf(b1.y, w.y, a1[1]);
        a2[1] = fmaf(b1.z, w.z, a2[1]); a3[1] = fmaf(b1.w, w.w, a3[1]);
        a0[2] = fmaf(b2.x, w.x, a0[2]); a1[2] = fmaf(b2.y, w.y, a1[2]);
        a2[2] = fmaf(b2.z, w.z, a2[2]); a3[2] = fmaf(b2.w, w.w, a3[2]);
        a0[3] = fmaf(b3.x, w.x, a0[3]); a1[3] = fmaf(b3.y, w.y, a1[3]);
        a2[3] = fmaf(b3.z, w.z, a2[3]); a3[3] = fmaf(b3.w, w.w, a3[3]);
    }
    #pragma unroll
    for (int j = 0; j < 4; j++)
        g_zx[(m0 + j) * 32 + t] = (a0[j] + a1[j]) + (a2[j] + a3[j]);
}

// ---------------------------------------------------------------------------
// Kernel 2: sequential LSTM scan (R10, unchanged). One warp per chain.
// ---------------------------------------------------------------------------
__global__ __launch_bounds__(32) void scan_kernel(
    const float* __restrict__ Win, const float* __restrict__ Wout,
    const float* __restrict__ b_out)
{
    int b = blockIdx.x;
    int t = threadIdx.x;
    int g = t >> 3, q = t & 7;

    float wh[8], wo[8];
    #pragma unroll
    for (int j = 0; j < 8; j++) wh[j] = Win[t * 72 + 64 + j];
    #pragma unroll
    for (int j = 0; j < 8; j++) wo[j] = Wout[t * 8 + j];
    float bo = b_out[t];

    float h = 0.f, c = 0.f;
    float zn = g_zx[b * 32 + t];

    for (int s = 0; s < S_LEN; s++) {
        float z = zn;
        if (s + 1 < S_LEN) zn = g_zx[((s + 1) * B_SZ + b) * 32 + t];
        float h0 = __shfl_sync(~0u, h, 0), h1 = __shfl_sync(~0u, h, 1);
        float h2 = __shfl_sync(~0u, h, 2), h3 = __shfl_sync(~0u, h, 3);
        float h4 = __shfl_sync(~0u, h, 4), h5 = __shfl_sync(~0u, h, 5);
        float h6 = __shfl_sync(~0u, h, 6), h7 = __shfl_sync(~0u, h, 7);
        float a0 = fmaf(h0, wh[0], fmaf(h1, wh[1], fmaf(h2, wh[2], h3 * wh[3])));
        float a1 = fmaf(h4, wh[4], fmaf(h5, wh[5], fmaf(h6, wh[6], h7 * wh[7])));
        z = z + a0 + a1;

        float p = __cosf(z);
        float cj[8];
        #pragma unroll
        for (int j = 0; j < 8; j++) cj[j] = __shfl_sync(~0u, p, (g << 3) + j);
        float A = fmaf(cj[1], fmaf(cj[2], fmaf(cj[3], wo[3], wo[2]), wo[1]), wo[0]);
        float B = fmaf(cj[5], fmaf(cj[6], fmaf(cj[7], wo[7], wo[6]), wo[5]), wo[4]);
        float q01 = cj[0] * cj[1], q23 = cj[2] * cj[3];
        float Q = q01 * q23 * cj[4];
        float pre = fmaf(Q, B, fmaf(cj[0], A, bo));

        float act = (g == 2) ? fast_tanh(pre) : fast_sigmoid(pre);
        float af = __shfl_sync(~0u, act, q);
        float ii = __shfl_sync(~0u, act, 8 + q);
        float ag = __shfl_sync(~0u, act, 16 + q);
        float ao = __shfl_sync(~0u, act, 24 + q);
        c = fmaf(af, c, ii * ag);
        h = ao * fast_tanh(c);
        if (t < 8) g_h[(s * B_SZ + b) * H_DIM + t] = h;
    }
}

// ---------------------------------------------------------------------------
// Quantum head primitives (compile-time specialized).
// ---------------------------------------------------------------------------
template <int LM>
__device__ __forceinline__ void u2_lane_t(float (&ar)[8], float (&ai)[8],
                                          int lane, const float* __restrict__ u) {
    int myb = (lane & LM) ? 1 : 0;
    float dr = myb ? u[6] : u[0];
    float di = myb ? u[7] : u[1];
    float orr= myb ? u[4] : u[2];
    float oi = myb ? u[5] : u[3];
    #pragma unroll
    for (int r = 0; r < 8; r++) {
        float pr = __shfl_xor_sync(~0u, ar[r], LM);
        float pi = __shfl_xor_sync(~0u, ai[r], LM);
        float nr = dr * ar[r] - di * ai[r] + orr * pr - oi * pi;
        float ni = dr * ai[r] + di * ar[r] + orr * pi + oi * pr;
        ar[r] = nr; ai[r] = ni;
    }
}

template <int TM>
__device__ __forceinline__ void u2_reg_t(float (&ar)[8], float (&ai)[8],
                                         const float* __restrict__ u) {
    #pragma unroll
    for (int r = 0; r < 8; r++) {
        if ((r & TM) == 0) {
            const int r1 = r | TM;
            float a0r = ar[r], a0i = ai[r], a1r = ar[r1], a1i = ai[r1];
            ar[r]  = u[0]*a0r - u[1]*a0i + u[2]*a1r - u[3]*a1i;
            ai[r]  = u[0]*a0i + u[1]*a0r + u[2]*a1i + u[3]*a1r;
            ar[r1] = u[4]*a0r - u[5]*a0i + u[6]*a1r - u[7]*a1i;
            ai[r1] = u[4]*a0i + u[5]*a0r + u[6]*a1i + u[7]*a1r;
        }
    }
}

template <int P>
__device__ __forceinline__ void rz_t(float (&ar)[8], float (&ai)[8],
                                     int lane, float c, float s) {
    #pragma unroll
    for (int r = 0; r < 8; r++) {
        bool beta;
        if constexpr (P >= 3) beta = (lane >> (P - 3)) & 1;
        else                  beta = (r >> P) & 1;
        float sg = beta ? -s : s;
        float nr = fmaf(c, ar[r],  sg * ai[r]);
        float ni = fmaf(c, ai[r], -sg * ar[r]);
        ar[r] = nr; ai[r] = ni;
    }
}

template <int CM, int TM>
__device__ __forceinline__ void cnot_rr_tt(float (&ar)[8], float (&ai)[8]) {
    #pragma unroll
    for (int r = 0; r < 8; r++) {
        if (((r & CM) != 0) && ((r & TM) == 0)) {
            const int r1 = r | TM;
            float tr = ar[r]; ar[r] = ar[r1]; ar[r1] = tr;
            float ti = ai[r]; ai[r] = ai[r1]; ai[r1] = ti;
        }
    }
}

template <int TM>
__device__ __forceinline__ void cnot_lr_tt(float (&ar)[8], float (&ai)[8], int ctrl) {
    #pragma unroll
    for (int r = 0; r < 8; r++) {
        if ((r & TM) == 0) {
            const int r1 = r | TM;
            float tr = ctrl ? ar[r1] : ar[r];
            float t2 = ctrl ? ar[r]  : ar[r1];
            ar[r] = tr; ar[r1] = t2;
            float ti = ctrl ? ai[r1] : ai[r];
            float t3 = ctrl ? ai[r]  : ai[r1];
            ai[r] = ti; ai[r1] = t3;
        }
    }
}

template <int CM, int LT>
__device__ __forceinline__ void cnot_rl_tt(float (&ar)[8], float (&ai)[8]) {
    #pragma unroll
    for (int r = 0; r < 8; r++) {
        if ((r & CM) != 0) {
            float sr = __shfl_xor_sync(~0u, ar[r], LT);
            float si = __shfl_xor_sync(~0u, ai[r], LT);
            ar[r] = sr; ai[r] = si;
        }
    }
}

template <int CM, int LT>
__device__ __forceinline__ void cnot_ll_tt(float (&ar)[8], float (&ai)[8], int lane) {
    int ctrl = (lane & CM) != 0;
    #pragma unroll
    for (int r = 0; r < 8; r++) {
        float sr = __shfl_xor_sync(~0u, ar[r], LT);
        float si = __shfl_xor_sync(~0u, ai[r], LT);
        if (ctrl) { ar[r] = sr; ai[r] = si; }
    }
}

template <int TM>
__device__ __forceinline__ void rx_reg(float (&ar)[8], float (&ai)[8], float c, float s) {
    #pragma unroll
    for (int r = 0; r < 8; r++) {
        if ((r & TM) == 0) {
            const int r1 = r | TM;
            float a0r = ar[r], a0i = ai[r], a1r = ar[r1], a1i = ai[r1];
            ar[r]  = fmaf(c, a0r,  s * a1i);  ai[r]  = fmaf(c, a0i, -s * a1r);
            ar[r1] = fmaf(c, a1r,  s * a0i);  ai[r1] = fmaf(c, a1i, -s * a0r);
        }
    }
}

template <int LM>
__device__ __forceinline__ void rx_lane(float (&ar)[8], float (&ai)[8], float c, float s) {
    #pragma unroll
    for (int r = 0; r < 8; r++) {
        float pr = __shfl_xor_sync(~0u, ar[r], LM);
        float pi = __shfl_xor_sync(~0u, ai[r], LM);
        float nr = fmaf(c, ar[r],  s * pi);
        float ni = fmaf(c, ai[r], -s * pr);
        ar[r] = nr; ai[r] = ni;
    }
}

template <int O>
__device__ __forceinline__ void apply_all(float (&ar)[8], float (&ai)[8],
                                          int lane, const float* __restrict__ U) {
    if constexpr (O < EM.n) {
        constexpr int TY = EM.type[O];
        constexpr int A  = EM.a[O];
        constexpr int B  = EM.b[O];
        if constexpr (TY == 1) {
            constexpr int PC = 7 - A, PT = 7 - B;
            if constexpr (PT < 3) {
                if constexpr (PC < 3) cnot_rr_tt<(1 << PC), (1 << PT)>(ar, ai);
                else cnot_lr_tt<(1 << PT)>(ar, ai, (lane >> (PC - 3)) & 1);
            } else {
                if constexpr (PC < 3) cnot_rl_tt<(1 << PC), (1 << (PT - 3))>(ar, ai);
                else cnot_ll_tt<(1 << (PC - 3)), (1 << (PT - 3))>(ar, ai, lane);
            }
        } else if constexpr (TY == 2) {
            rz_t<7 - A>(ar, ai, lane, U[O * 8 + 0], U[O * 8 + 1]);
        } else {
            constexpr int P = 7 - A;
            if constexpr (P < 3) u2_reg_t<(1 << P)>(ar, ai, U + O * 8);
            else u2_lane_t<(1 << (P - 3))>(ar, ai, lane, U + O * 8);
        }
        apply_all<O + 1>(ar, ai, lane, U);
    }
}

// ---------------------------------------------------------------------------
// Kernel 3: quantum head + log-softmax (R10, unchanged). One warp per row.
// ---------------------------------------------------------------------------
__global__ __launch_bounds__(128) void head_kernel(
    const float* __restrict__ phiq, const float* __restrict__ Whead,
    const float* __restrict__ b_head, float* __restrict__ out, QU P)
{
    int warp = (blockIdx.x * blockDim.x + threadIdx.x) >> 5;
    int lane = threadIdx.x & 31;
    int s_out = warp >> 7, b_out = warp & 127;
    const float* hsrc = g_h + ((b_out << 7) + s_out) * H_DIM;

    float myc = 1.f, mys = 0.f;
    if (lane < 8) __sincosf(hsrc[lane] * 0.5f, &mys, &myc);
    float lp = 1.f;
    #pragma unroll
    for (int w = 0; w < 5; w++) {
        float cw = __shfl_sync(~0u, myc, w);
        float sw = __shfl_sync(~0u, mys, w);
        lp *= ((lane >> (4 - w)) & 1) ? sw : cw;
    }
    float c5 = __shfl_sync(~0u, myc, 5), s5 = __shfl_sync(~0u, mys, 5);
    float c6 = __shfl_sync(~0u, myc, 6), s6 = __shfl_sync(~0u, mys, 6);
    float c7 = __shfl_sync(~0u, myc, 7), s7 = __shfl_sync(~0u, mys, 7);

    float ar[8], ai[8];
    #pragma unroll
    for (int r = 0; r < 8; r++) {
        ar[r] = lp * ((r & 4) ? s5 : c5) * ((r & 2) ? s6 : c6) * ((r & 1) ? s7 : c7);
        ai[r] = 0.f;
    }

    apply_all<0>(ar, ai, lane, P.u);

    float pc = 1.f, ps = 0.f;
    if (lane < 8) __sincosf(phiq[lane] * 0.5f, &ps, &pc);
    {
        float cw, sw;
        cw = __shfl_sync(~0u, pc, 0); sw = __shfl_sync(~0u, ps, 0); rx_lane<16>(ar, ai, cw, sw);
        cw = __shfl_sync(~0u, pc, 1); sw = __shfl_sync(~0u, ps, 1); rx_lane<8>(ar, ai, cw, sw);
        cw = __shfl_sync(~0u, pc, 2); sw = __shfl_sync(~0u, ps, 2); rx_lane<4>(ar, ai, cw, sw);
        cw = __shfl_sync(~0u, pc, 3); sw = __shfl_sync(~0u, ps, 3); rx_lane<2>(ar, ai, cw, sw);
        cw = __shfl_sync(~0u, pc, 4); sw = __shfl_sync(~0u, ps, 4); rx_lane<1>(ar, ai, cw, sw);
        cw = __shfl_sync(~0u, pc, 5); sw = __shfl_sync(~0u, ps, 5); rx_reg<4>(ar, ai, cw, sw);
        cw = __shfl_sync(~0u, pc, 6); sw = __shfl_sync(~0u, ps, 6); rx_reg<2>(ar, ai, cw, sw);
        cw = __shfl_sync(~0u, pc, 7); sw = __shfl_sync(~0u, ps, 7); rx_reg<1>(ar, ai, cw, sw);
    }

    float p[8], tot = 0.f;
    #pragma unroll
    for (int r = 0; r < 8; r++) {
        p[r] = ar[r] * ar[r] + ai[r] * ai[r];
        tot += p[r];
    }
    float z5 = (p[0] + p[1] + p[2] + p[3]) - (p[4] + p[5] + p[6] + p[7]);
    float z6 = (p[0] + p[1] + p[4] + p[5]) - (p[2] + p[3] + p[6] + p[7]);
    float z7 = (p[0] + p[2] + p[4] + p[6]) - (p[1] + p[3] + p[5] + p[7]);

    float v = tot;
    #pragma unroll
    for (int mm = 1; mm < 32; mm <<= 1) {
        float tt = __shfl_xor_sync(~0u, v, mm);
        v = (lane & mm) ? (tt - v) : (tt + v);
    }
    #pragma unroll
    for (int off = 16; off; off >>= 1) {
        z5 += __shfl_xor_sync(~0u, z5, off);
        z6 += __shfl_xor_sync(~0u, z6, off);
        z7 += __shfl_xor_sync(~0u, z7, off);
    }
    float z[8];
    z[0] = __shfl_sync(~0u, v, 16);
    z[1] = __shfl_sync(~0u, v, 8);
    z[2] = __shfl_sync(~0u, v, 4);
    z[3] = __shfl_sync(~0u, v, 2);
    z[4] = __shfl_sync(~0u, v, 1);
    z[5] = z5; z[6] = z6; z[7] = z7;

    float logit = -1e30f;
    if (lane < 12) {
        logit = b_head[lane];
        #pragma unroll
        for (int k = 0; k < 8; k++) logit = fmaf(z[k], Whead[lane * 8 + k], logit);
    }
    float mx = logit;
    #pragma unroll
    for (int off = 8; off; off >>= 1) mx = fmaxf(mx, __shfl_xor_sync(~0u, mx, off, 16));
    float e = (lane < 12) ? __expf(logit - mx) : 0.f;
    float se = e;
    #pragma unroll
    for (int off = 8; off; off >>= 1) se += __shfl_xor_sync(~0u, se, off, 16);
    if (lane < 12) out[warp * T_OUT + lane] = logit - mx - __logf(se);
}

// ---------------------------------------------------------------------------
// Host: numpy-legacy MT19937 (RandomState(1234)) + gate fusion -> coefficients.
// ---------------------------------------------------------------------------
namespace {
struct MTState { uint32_t mt[624]; int mti; };

static void mt_seed(MTState& s, uint32_t seed) {
    s.mt[0] = seed;
    for (int i = 1; i < 624; i++)
        s.mt[i] = 1812433253u * (s.mt[i - 1] ^ (s.mt[i - 1] >> 30)) + (uint32_t)i;
    s.mti = 624;
}
static uint32_t mt_next(MTState& s) {
    if (s.mti >= 624) {
        for (int i = 0; i < 624; i++) {
            uint32_t y = (s.mt[i] & 0x80000000u) | (s.mt[(i + 1) % 624] & 0x7fffffffu);
            s.mt[i] = s.mt[(i + 397) % 624] ^ (y >> 1) ^ ((y & 1u) ? 0x9908b0dfu : 0u);
        }
        s.mti = 0;
    }
    uint32_t y = s.mt[s.mti++];
    y ^= y >> 11;
    y ^= (y << 7) & 0x9d2c5680u;
    y ^= (y << 15) & 0xefc60000u;
    y ^= y >> 18;
    return y;
}
static uint32_t np_randint(MTState& s, uint32_t n) {
    uint32_t rng = n - 1;
    uint32_t mask = rng;
    mask |= mask >> 1; mask |= mask >> 2; mask |= mask >> 4;
    mask |= mask >> 8; mask |= mask >> 16;
    uint32_t v;
    do { v = mt_next(s) & mask; } while (v > rng);
    return v;
}
static double np_double(MTState& s) {
    uint32_t a = mt_next(s) >> 5;
    uint32_t b = mt_next(s) >> 6;
    return ((double)a * 67108864.0 + (double)b) / 9007199254740992.0;
}

typedef std::complex<double> cd;

struct Pend {
    cd m[2][2];
    int count;
    bool allrz;
    void reset() { m[0][0] = 1.0; m[0][1] = 0.0; m[1][0] = 0.0; m[1][1] = 1.0; count = 0; allrz = true; }
};

static void build_u(QU& P) {
    MTState m;
    mt_seed(m, 1234u);

    Pend pend[8];
    for (int w = 0; w < 8; w++) pend[w].reset();
    int n = 0;

    auto flush = [&](int w) {
        if (!pend[w].count) return;
        float* u = &P.u[n * 8];
        if (pend[w].allrz) {
            u[0] = (float)pend[w].m[0][0].real();
            u[1] = (float)(-pend[w].m[0][0].imag());
        } else {
            u[0] = (float)pend[w].m[0][0].real(); u[1] = (float)pend[w].m[0][0].imag();
            u[2] = (float)pend[w].m[0][1].real(); u[3] = (float)pend[w].m[0][1].imag();
            u[4] = (float)pend[w].m[1][0].real(); u[5] = (float)pend[w].m[1][0].imag();
            u[6] = (float)pend[w].m[1][1].real(); u[7] = (float)pend[w].m[1][1].imag();
        }
        n++;
        pend[w].reset();
    };

    for (int k = 0; k < N_RAW; k++) {
        uint32_t kind = np_randint(m, 4);
        if (kind == 3) {
            int c = (int)np_randint(m, 8);
            int t = (int)np_randint(m, 7);
            if (t >= c) t++;
            flush(c); flush(t);
            n++;                       // CNOT slot (no coefficients)
        } else {
            int g = (int)(kind % 3);
            int w = (int)np_randint(m, 8);
            double ang = 6.283185307179586 * np_double(m);
            double th = (double)(float)ang;
            double c = cos(th * 0.5), s = sin(th * 0.5);
            cd R[2][2];
            if (g == 0) {
                R[0][0] = c; R[0][1] = cd(0, -s);
                R[1][0] = cd(0, -s); R[1][1] = c;
            } else if (g == 1) {
                R[0][0] = c; R[0][1] = -s;
                R[1][0] = s; R[1][1] = c;
            } else {
                R[0][0] = cd(c, -s); R[0][1] = 0.0;
                R[1][0] = 0.0; R[1][1] = cd(c, s);
            }
            cd n00 = R[0][0] * pend[w].m[0][0] + R[0][1] * pend[w].m[1][0];
            cd n01 = R[0][0] * pend[w].m[0][1] + R[0][1] * pend[w].m[1][1];
            cd n10 = R[1][0] * pend[w].m[0][0] + R[1][1] * pend[w].m[1][0];
            cd n11 = R[1][0] * pend[w].m[0][1] + R[1][1] * pend[w].m[1][1];
            pend[w].m[0][0] = n00; pend[w].m[0][1] = n01;
            pend[w].m[1][0] = n10; pend[w].m[1][1] = n11;
            pend[w].count++;
            if (g != 2) pend[w].allrz = false;
        }
    }
    for (int w = 0; w < 8; w++) flush(w);
}
} // namespace

// ---------------------------------------------------------------------------
extern "C" void kernel_launch(void* const* d_in, const int* in_sizes, int n_in,
                              void* d_out, int out_size) {
    (void)in_sizes; (void)n_in; (void)out_size;
    const float* emb    = (const float*)d_in[0];
    const float* Win    = (const float*)d_in[1];
    const float* b_in   = (const float*)d_in[2];
    const float* phi    = (const float*)d_in[3];
    const float* Wout   = (const float*)d_in[4];
    const float* b_out  = (const float*)d_in[5];
    const float* phiq   = (const float*)d_in[6];
    const float* Whead  = (const float*)d_in[7];
    const float* b_head = (const float*)d_in[8];
    const int*   sent   = (const int*)d_in[9];

    QU P{};
    build_u(P);

    zx_kernel<<<NROWS / 32, 256>>>(emb, Win, b_in, phi, sent);
    scan_kernel<<<B_SZ, 32>>>(Win, Wout, b_out);
    head_kernel<<<NROWS / 4, 128>>>(phiq, Whead, b_head, (float*)d_out, P);
}

// round 15
// speedup vs baseline: 2.1601x; 1.0907x over previous
#include <cuda_runtime.h>
#include <cstdint>
#include <math.h>
#include <complex>

// Problem constants
#define S_LEN 128
#define B_SZ  128
#define H_DIM 8
#define T_OUT 12
#define NROWS (S_LEN * B_SZ)
#define N_RAW 30
#define MAX_EMIT 40

// ---------------------------------------------------------------------------
// Device scratch
// ---------------------------------------------------------------------------
__device__ float g_zx[NROWS * 32];
__device__ float g_h[NROWS * H_DIM];
__device__ float g_fu[64];              // fused RX(phiq)*U coefficients per wire

struct QU { float u[MAX_EMIT * 8]; };   // fused-op coefficients, host-computed

// ---------------------------------------------------------------------------
// Compile-time MT19937 + random-layer structure (types/wires only; no floats).
// ---------------------------------------------------------------------------
struct EmitList { int n; int type[MAX_EMIT]; int a[MAX_EMIT]; int b[MAX_EMIT]; };

constexpr uint32_t cmt_next(uint32_t (&mt)[624], int& mti) {
    if (mti >= 624) {
        for (int i = 0; i < 624; i++) {
            uint32_t y = (mt[i] & 0x80000000u) | (mt[(i + 1) % 624] & 0x7fffffffu);
            mt[i] = mt[(i + 397) % 624] ^ (y >> 1) ^ ((y & 1u) ? 0x9908b0dfu : 0u);
        }
        mti = 0;
    }
    uint32_t y = mt[mti++];
    y ^= y >> 11;
    y ^= (y << 7) & 0x9d2c5680u;
    y ^= (y << 15) & 0xefc60000u;
    y ^= y >> 18;
    return y;
}
constexpr uint32_t c_randint(uint32_t (&mt)[624], int& mti, uint32_t n) {
    uint32_t rng = n - 1;
    uint32_t mask = rng;
    mask |= mask >> 1; mask |= mask >> 2; mask |= mask >> 4;
    mask |= mask >> 8; mask |= mask >> 16;
    uint32_t v = cmt_next(mt, mti) & mask;
    while (v > rng) v = cmt_next(mt, mti) & mask;
    return v;
}

constexpr EmitList compute_emitted() {
    uint32_t mt[624] = {};
    mt[0] = 1234u;
    for (int i = 1; i < 624; i++)
        mt[i] = 1812433253u * (mt[i - 1] ^ (mt[i - 1] >> 30)) + (uint32_t)i;
    int mti = 624;

    EmitList E{};
    int cnt[8] = {};
    bool allrz[8] = {true, true, true, true, true, true, true, true};

    for (int k = 0; k < N_RAW; k++) {
        uint32_t kind = c_randint(mt, mti, 4);
        if (kind == 3) {
            int c = (int)c_randint(mt, mti, 8);
            int t = (int)c_randint(mt, mti, 7);
            if (t >= c) t++;
            if (cnt[c]) { E.type[E.n] = allrz[c] ? 2 : 0; E.a[E.n] = c; E.b[E.n] = 0; E.n++; cnt[c] = 0; allrz[c] = true; }
            if (cnt[t]) { E.type[E.n] = allrz[t] ? 2 : 0; E.a[E.n] = t; E.b[E.n] = 0; E.n++; cnt[t] = 0; allrz[t] = true; }
            E.type[E.n] = 1; E.a[E.n] = c; E.b[E.n] = t; E.n++;
        } else {
            int g = (int)(kind % 3);
            int w = (int)c_randint(mt, mti, 8);
            cmt_next(mt, mti); cmt_next(mt, mti);   // uniform() draws
            cnt[w]++;
            if (g != 2) allrz[w] = false;
        }
    }
    for (int w = 0; w < 8; w++)
        if (cnt[w]) { E.type[E.n] = allrz[w] ? 2 : 0; E.a[E.n] = w; E.b[E.n] = 0; E.n++; }
    return E;
}

constexpr EmitList EM = compute_emitted();

// Fusion metadata as a constexpr VARIABLE (device-readable, unlike functions).
struct FuseInfo { int lastop[8]; bool fus[8]; int fuseat[MAX_EMIT]; };
constexpr FuseInfo compute_fuse() {
    FuseInfo F{};
    for (int w = 0; w < 8; w++) {
        int last = -1;
        for (int i = 0; i < EM.n; i++) {
            if (EM.type[i] == 1) { if (EM.a[i] == w || EM.b[i] == w) last = i; }
            else                 { if (EM.a[i] == w) last = i; }
        }
        F.lastop[w] = last;
        F.fus[w] = (last >= 0 && EM.type[last] != 1);
    }
    for (int o = 0; o < MAX_EMIT; o++) {
        F.fuseat[o] = -1;
        for (int w = 0; w < 8; w++)
            if (F.fus[w] && F.lastop[w] == o) F.fuseat[o] = w;
    }
    return F;
}
constexpr FuseInfo FI = compute_fuse();

// ---------------------------------------------------------------------------
// Fast helpers
// ---------------------------------------------------------------------------
__device__ __forceinline__ float fast_rcp(float x){ float r; asm("rcp.approx.f32 %0,%1;":"=f"(r):"f"(x)); return r; }
__device__ __forceinline__ float fast_ex2(float x){ float r; asm("ex2.approx.f32 %0,%1;":"=f"(r):"f"(x)); return r; }
__device__ __forceinline__ float fast_exp(float x){ return fast_ex2(x * 1.4426950408889634f); }
__device__ __forceinline__ float fast_sigmoid(float x){ return fast_rcp(1.f + fast_exp(-x)); }

// ---------------------------------------------------------------------------
// RX(phiq) fusion: computed by zx_kernel block 0 / warp 7 (before head runs).
// F = RX(phiq_w) * U_last(w); stored to g_fu[w*8..].
// ---------------------------------------------------------------------------
template <int W>
__device__ __forceinline__ void fuse_chain(int lane, const float* __restrict__ phiq,
                                           const float* __restrict__ U) {
    if constexpr (FI.fus[W]) {
        if (lane == W) {
            constexpr int O = FI.lastop[W];
            float s, c;
            __sincosf(phiq[W] * 0.5f, &s, &c);
            float u0, u1, u2, u3, u4, u5, u6, u7;
            if constexpr (EM.type[O] == 2) {
                float cz = U[O * 8 + 0], sz = U[O * 8 + 1];
                u0 = cz; u1 = -sz; u2 = 0.f; u3 = 0.f;
                u4 = 0.f; u5 = 0.f; u6 = cz; u7 = sz;
            } else {
                u0 = U[O * 8 + 0]; u1 = U[O * 8 + 1]; u2 = U[O * 8 + 2]; u3 = U[O * 8 + 3];
                u4 = U[O * 8 + 4]; u5 = U[O * 8 + 5]; u6 = U[O * 8 + 6]; u7 = U[O * 8 + 7];
            }
            // RX = [[c, -i s], [-i s, c]];  F = RX * U
            g_fu[W * 8 + 0] = c * u0 + s * u5;
            g_fu[W * 8 + 1] = c * u1 - s * u4;
            g_fu[W * 8 + 2] = c * u2 + s * u7;
            g_fu[W * 8 + 3] = c * u3 - s * u6;
            g_fu[W * 8 + 4] = c * u4 + s * u1;
            g_fu[W * 8 + 5] = c * u5 - s * u0;
            g_fu[W * 8 + 6] = c * u6 + s * u3;
            g_fu[W * 8 + 7] = c * u7 - s * u2;
        }
    }
    if constexpr (W < 7) fuse_chain<W + 1>(lane, phiq, U);
}

// ---------------------------------------------------------------------------
// Kernel 1: zx (MLP=4 body) + RX fusion side-task.
// ---------------------------------------------------------------------------
__global__ __launch_bounds__(256) void zx_kernel(
    const float* __restrict__ emb, const float* __restrict__ Win,
    const float* __restrict__ b_in, const float* __restrict__ phi,
    const int* __restrict__ sent32, const float* __restrict__ phiq, QU P)
{
    __shared__ float4 sW4[32 * 17];
    __shared__ float4 sx4[32 * 17];
    __shared__ float  sBP[32];
    __shared__ int    sIs64;

    int tid = threadIdx.x, lane = tid & 31, wid = tid >> 5;

    if (wid == 0) {
        int acc = sent32[2 * lane + 1] | sent32[2 * (lane + 32) + 1];
        #pragma unroll
        for (int off = 16; off; off >>= 1) acc |= __shfl_xor_sync(~0u, acc, off);
        if (lane == 0) sIs64 = (acc == 0) ? 1 : 0;
    }
    if (blockIdx.x == 0 && wid == 7) fuse_chain<0>(lane, phiq, P.u);

    for (int i = tid; i < 512; i += 256) {
        int t = i >> 4, k = i & 15;
        sW4[t * 17 + k] = ((const float4*)(Win + t * 72))[k];
    }
    if (tid < 32) sBP[tid] = b_in[tid] + phi[tid];
    __syncthreads();

    int m0 = blockIdx.x * 32 + wid * 4;
    int r = lane >> 3;
    int kk = lane & 7;
    int m = m0 + r;
    int tok = sIs64 ? sent32[2 * m] : sent32[m];
    const float4* xsrc = (const float4*)(emb + (size_t)tok * 64);
    float4 v0 = xsrc[kk];
    float4 v1 = xsrc[kk + 8];
    sx4[(wid * 4 + r) * 17 + kk]     = v0;
    sx4[(wid * 4 + r) * 17 + kk + 8] = v1;
    __syncwarp();

    int t = lane;
    float bp = sBP[t];
    float a0[4], a1[4], a2[4], a3[4];
    #pragma unroll
    for (int j = 0; j < 4; j++) { a0[j] = bp; a1[j] = 0.f; a2[j] = 0.f; a3[j] = 0.f; }

    const float4* wr = &sW4[t * 17];
    const float4* x0 = &sx4[(wid * 4 + 0) * 17];
    const float4* x1 = &sx4[(wid * 4 + 1) * 17];
    const float4* x2 = &sx4[(wid * 4 + 2) * 17];
    const float4* x3 = &sx4[(wid * 4 + 3) * 17];
    #pragma unroll
    for (int k = 0; k < 16; k++) {
        float4 w  = wr[k];
        float4 b0 = x0[k], b1 = x1[k], b2 = x2[k], b3 = x3[k];
        a0[0] = fmaf(b0.x, w.x, a0[0]); a1[0] = fmaf(b0.y, w.y, a1[0]);
        a2[0] = fmaf(b0.z, w.z, a2[0]); a3[0] = fmaf(b0.w, w.w, a3[0]);
        a0[1] = fmaf(b1.x, w.x, a0[1]); a1[1] = fmaf(b1.y, w.y, a1[1]);
        a2[1] = fmaf(b1.z, w.z, a2[1]); a3[1] = fmaf(b1.w, w.w, a3[1]);
        a0[2] = fmaf(b2.x, w.x, a0[2]); a1[2] = fmaf(b2.y, w.y, a1[2]);
        a2[2] = fmaf(b2.z, w.z, a2[2]); a3[2] = fmaf(b2.w, w.w, a3[2]);
        a0[3] = fmaf(b3.x, w.x, a0[3]); a1[3] = fmaf(b3.y, w.y, a1[3]);
        a2[3] = fmaf(b3.z, w.z, a2[3]); a3[3] = fmaf(b3.w, w.w, a3[3]);
    }
    #pragma unroll
    for (int j = 0; j < 4; j++)
        g_zx[(m0 + j) * 32 + t] = (a0[j] + a1[j]) + (a2[j] + a3[j]);
}

// ---------------------------------------------------------------------------
// Kernel 2: sequential LSTM scan. tanh via 2*sigmoid(2x)-1 (exact identity).
// ---------------------------------------------------------------------------
__global__ __launch_bounds__(32) void scan_kernel(
    const float* __restrict__ Win, const float* __restrict__ Wout,
    const float* __restrict__ b_out)
{
    int b = blockIdx.x;
    int t = threadIdx.x;
    int g = t >> 3, q = t & 7;

    float wh[8], wo[8];
    #pragma unroll
    for (int j = 0; j < 8; j++) wh[j] = Win[t * 72 + 64 + j];
    #pragma unroll
    for (int j = 0; j < 8; j++) wo[j] = Wout[t * 8 + j];
    float bo = b_out[t];

    float h = 0.f, c = 0.f;
    float zn = g_zx[b * 32 + t];

    for (int s = 0; s < S_LEN; s++) {
        float z = zn;
        if (s + 1 < S_LEN) zn = g_zx[((s + 1) * B_SZ + b) * 32 + t];
        float h0 = __shfl_sync(~0u, h, 0), h1 = __shfl_sync(~0u, h, 1);
        float h2 = __shfl_sync(~0u, h, 2), h3 = __shfl_sync(~0u, h, 3);
        float h4 = __shfl_sync(~0u, h, 4), h5 = __shfl_sync(~0u, h, 5);
        float h6 = __shfl_sync(~0u, h, 6), h7 = __shfl_sync(~0u, h, 7);
        float a0 = fmaf(h0, wh[0], fmaf(h1, wh[1], fmaf(h2, wh[2], h3 * wh[3])));
        float a1 = fmaf(h4, wh[4], fmaf(h5, wh[5], fmaf(h6, wh[6], h7 * wh[7])));
        z = z + a0 + a1;

        float p = __cosf(z);
        float cj[8];
        #pragma unroll
        for (int j = 0; j < 8; j++) cj[j] = __shfl_sync(~0u, p, (g << 3) + j);
        float A = fmaf(cj[1], fmaf(cj[2], fmaf(cj[3], wo[3], wo[2]), wo[1]), wo[0]);
        float B = fmaf(cj[5], fmaf(cj[6], fmaf(cj[7], wo[7], wo[6]), wo[5]), wo[4]);
        float q01 = cj[0] * cj[1], q23 = cj[2] * cj[3];
        float Q = q01 * q23 * cj[4];
        float pre = fmaf(Q, B, fmaf(cj[0], A, bo));

        // uniform activation: sigma for gates, tanh = 2*sigma(2x)-1 for g==2
        float xx = (g == 2) ? 2.f * pre : pre;
        float sgv = fast_sigmoid(xx);
        float act = (g == 2) ? fmaf(2.f, sgv, -1.f) : sgv;

        float af = __shfl_sync(~0u, act, q);
        float ii = __shfl_sync(~0u, act, 8 + q);
        float ag = __shfl_sync(~0u, act, 16 + q);
        float ao = __shfl_sync(~0u, act, 24 + q);
        c = fmaf(af, c, ii * ag);
        float th = fmaf(2.f, fast_sigmoid(2.f * c), -1.f);
        h = ao * th;
        if (t < 8) g_h[(s * B_SZ + b) * H_DIM + t] = h;
    }
}

// ---------------------------------------------------------------------------
// Quantum head primitives (compile-time specialized).
// ---------------------------------------------------------------------------
template <int LM>
__device__ __forceinline__ void u2_lane_t(float (&ar)[8], float (&ai)[8],
                                          int lane, const float* __restrict__ u) {
    int myb = (lane & LM) ? 1 : 0;
    float dr = myb ? u[6] : u[0];
    float di = myb ? u[7] : u[1];
    float orr= myb ? u[4] : u[2];
    float oi = myb ? u[5] : u[3];
    #pragma unroll
    for (int r = 0; r < 8; r++) {
        float pr = __shfl_xor_sync(~0u, ar[r], LM);
        float pi = __shfl_xor_sync(~0u, ai[r], LM);
        float nr = dr * ar[r] - di * ai[r] + orr * pr - oi * pi;
        float ni = dr * ai[r] + di * ar[r] + orr * pi + oi * pr;
        ar[r] = nr; ai[r] = ni;
    }
}

template <int TM>
__device__ __forceinline__ void u2_reg_t(float (&ar)[8], float (&ai)[8],
                                         const float* __restrict__ u) {
    #pragma unroll
    for (int r = 0; r < 8; r++) {
        if ((r & TM) == 0) {
            const int r1 = r | TM;
            float a0r = ar[r], a0i = ai[r], a1r = ar[r1], a1i = ai[r1];
            ar[r]  = u[0]*a0r - u[1]*a0i + u[2]*a1r - u[3]*a1i;
            ai[r]  = u[0]*a0i + u[1]*a0r + u[2]*a1i + u[3]*a1r;
            ar[r1] = u[4]*a0r - u[5]*a0i + u[6]*a1r - u[7]*a1i;
            ai[r1] = u[4]*a0i + u[5]*a0r + u[6]*a1i + u[7]*a1r;
        }
    }
}

template <int P>
__device__ __forceinline__ void rz_t(float (&ar)[8], float (&ai)[8],
                                     int lane, float c, float s) {
    #pragma unroll
    for (int r = 0; r < 8; r++) {
        bool beta;
        if constexpr (P >= 3) beta = (lane >> (P - 3)) & 1;
        else                  beta = (r >> P) & 1;
        float sg = beta ? -s : s;
        float nr = fmaf(c, ar[r],  sg * ai[r]);
        float ni = fmaf(c, ai[r], -sg * ar[r]);
        ar[r] = nr; ai[r] = ni;
    }
}

template <int CM, int TM>
__device__ __forceinline__ void cnot_rr_tt(float (&ar)[8], float (&ai)[8]) {
    #pragma unroll
    for (int r = 0; r < 8; r++) {
        if (((r & CM) != 0) && ((r & TM) == 0)) {
            const int r1 = r | TM;
            float tr = ar[r]; ar[r] = ar[r1]; ar[r1] = tr;
            float ti = ai[r]; ai[r] = ai[r1]; ai[r1] = ti;
        }
    }
}

template <int TM>
__device__ __forceinline__ void cnot_lr_tt(float (&ar)[8], float (&ai)[8], int ctrl) {
    #pragma unroll
    for (int r = 0; r < 8; r++) {
        if ((r & TM) == 0) {
            const int r1 = r | TM;
            float tr = ctrl ? ar[r1] : ar[r];
            float t2 = ctrl ? ar[r]  : ar[r1];
            ar[r] = tr; ar[r1] = t2;
            float ti = ctrl ? ai[r1] : ai[r];
            float t3 = ctrl ? ai[r]  : ai[r1];
            ai[r] = ti; ai[r1] = t3;
        }
    }
}

template <int CM, int LT>
__device__ __forceinline__ void cnot_rl_tt(float (&ar)[8], float (&ai)[8]) {
    #pragma unroll
    for (int r = 0; r < 8; r++) {
        if ((r & CM) != 0) {
            float sr = __shfl_xor_sync(~0u, ar[r], LT);
            float si = __shfl_xor_sync(~0u, ai[r], LT);
            ar[r] = sr; ai[r] = si;
        }
    }
}

template <int CM, int LT>
__device__ __forceinline__ void cnot_ll_tt(float (&ar)[8], float (&ai)[8], int lane) {
    int ctrl = (lane & CM) != 0;
    #pragma unroll
    for (int r = 0; r < 8; r++) {
        float sr = __shfl_xor_sync(~0u, ar[r], LT);
        float si = __shfl_xor_sync(~0u, ai[r], LT);
        if (ctrl) { ar[r] = sr; ai[r] = si; }
    }
}

template <int TM>
__device__ __forceinline__ void rx_reg(float (&ar)[8], float (&ai)[8], float c, float s) {
    #pragma unroll
    for (int r = 0; r < 8; r++) {
        if ((r & TM) == 0) {
            const int r1 = r | TM;
            float a0r = ar[r], a0i = ai[r], a1r = ar[r1], a1i = ai[r1];
            ar[r]  = fmaf(c, a0r,  s * a1i);  ai[r]  = fmaf(c, a0i, -s * a1r);
            ar[r1] = fmaf(c, a1r,  s * a0i);  ai[r1] = fmaf(c, a1i, -s * a0r);
        }
    }
}

template <int LM>
__device__ __forceinline__ void rx_lane(float (&ar)[8], float (&ai)[8], float c, float s) {
    #pragma unroll
    for (int r = 0; r < 8; r++) {
        float pr = __shfl_xor_sync(~0u, ar[r], LM);
        float pi = __shfl_xor_sync(~0u, ai[r], LM);
        float nr = fmaf(c, ar[r],  s * pi);
        float ni = fmaf(c, ai[r], -s * pr);
        ar[r] = nr; ai[r] = ni;
    }
}

// ---- fully unrolled random layer; fused final per-wire ops read g_fu ----
template <int O>
__device__ __forceinline__ void apply_all(float (&ar)[8], float (&ai)[8],
                                          int lane, const float* __restrict__ U) {
    if constexpr (O < EM.n) {
        constexpr int TY = EM.type[O];
        constexpr int A  = EM.a[O];
        constexpr int B  = EM.b[O];
        constexpr int FW = FI.fuseat[O];
        if constexpr (TY == 1) {
            constexpr int PC = 7 - A, PT = 7 - B;
            if constexpr (PT < 3) {
                if constexpr (PC < 3) cnot_rr_tt<(1 << PC), (1 << PT)>(ar, ai);
                else cnot_lr_tt<(1 << PT)>(ar, ai, (lane >> (PC - 3)) & 1);
            } else {
                if constexpr (PC < 3) cnot_rl_tt<(1 << PC), (1 << (PT - 3))>(ar, ai);
                else cnot_ll_tt<(1 << (PC - 3)), (1 << (PT - 3))>(ar, ai, lane);
            }
        } else if constexpr (FW >= 0) {
            // final op of wire FW, pre-multiplied with RX(phiq_FW) in g_fu
            constexpr int P_ = 7 - A;
            if constexpr (P_ < 3) u2_reg_t<(1 << P_)>(ar, ai, g_fu + FW * 8);
            else u2_lane_t<(1 << (P_ - 3))>(ar, ai, lane, g_fu + FW * 8);
        } else if constexpr (TY == 2) {
            rz_t<7 - A>(ar, ai, lane, U[O * 8 + 0], U[O * 8 + 1]);
        } else {
            constexpr int P_ = 7 - A;
            if constexpr (P_ < 3) u2_reg_t<(1 << P_)>(ar, ai, U + O * 8);
            else u2_lane_t<(1 << (P_ - 3))>(ar, ai, lane, U + O * 8);
        }
        apply_all<O + 1>(ar, ai, lane, U);
    }
}

// RX(phiq) only on wires NOT already fused into the circuit.
template <int W>
__device__ __forceinline__ void rx_chain(float (&ar)[8], float (&ai)[8],
                                         int lane, float pc, float ps) {
    if constexpr (!FI.fus[W]) {
        float cw = __shfl_sync(~0u, pc, W);
        float sw = __shfl_sync(~0u, ps, W);
        constexpr int P_ = 7 - W;
        if constexpr (P_ < 3) rx_reg<(1 << P_)>(ar, ai, cw, sw);
        else rx_lane<(1 << (P_ - 3))>(ar, ai, cw, sw);
    }
    if constexpr (W < 7) rx_chain<W + 1>(ar, ai, lane, pc, ps);
}

// ---------------------------------------------------------------------------
// Kernel 3: quantum head + log-softmax. One warp per output row.
// ---------------------------------------------------------------------------
__global__ __launch_bounds__(128) void head_kernel(
    const float* __restrict__ phiq, const float* __restrict__ Whead,
    const float* __restrict__ b_head, float* __restrict__ out, QU P)
{
    int warp = (blockIdx.x * blockDim.x + threadIdx.x) >> 5;
    int lane = threadIdx.x & 31;
    int s_out = warp >> 7, b_out = warp & 127;
    const float* hsrc = g_h + ((b_out << 7) + s_out) * H_DIM;

    float myc = 1.f, mys = 0.f;
    if (lane < 8) __sincosf(hsrc[lane] * 0.5f, &mys, &myc);
    float lp = 1.f;
    #pragma unroll
    for (int w = 0; w < 5; w++) {
        float cw = __shfl_sync(~0u, myc, w);
        float sw = __shfl_sync(~0u, mys, w);
        lp *= ((lane >> (4 - w)) & 1) ? sw : cw;
    }
    float c5 = __shfl_sync(~0u, myc, 5), s5 = __shfl_sync(~0u, mys, 5);
    float c6 = __shfl_sync(~0u, myc, 6), s6 = __shfl_sync(~0u, mys, 6);
    float c7 = __shfl_sync(~0u, myc, 7), s7 = __shfl_sync(~0u, mys, 7);

    float ar[8], ai[8];
    #pragma unroll
    for (int r = 0; r < 8; r++) {
        ar[r] = lp * ((r & 4) ? s5 : c5) * ((r & 2) ? s6 : c6) * ((r & 1) ? s7 : c7);
        ai[r] = 0.f;
    }

    apply_all<0>(ar, ai, lane, P.u);

    float pc = 1.f, ps = 0.f;
    if (lane < 8) __sincosf(phiq[lane] * 0.5f, &ps, &pc);
    rx_chain<0>(ar, ai, lane, pc, ps);

    float p[8], tot = 0.f;
    #pragma unroll
    for (int r = 0; r < 8; r++) {
        p[r] = ar[r] * ar[r] + ai[r] * ai[r];
        tot += p[r];
    }
    float z5 = (p[0] + p[1] + p[2] + p[3]) - (p[4] + p[5] + p[6] + p[7]);
    float z6 = (p[0] + p[1] + p[4] + p[5]) - (p[2] + p[3] + p[6] + p[7]);
    float z7 = (p[0] + p[2] + p[4] + p[6]) - (p[1] + p[3] + p[5] + p[7]);

    float v = tot;
    #pragma unroll
    for (int mm = 1; mm < 32; mm <<= 1) {
        float tt = __shfl_xor_sync(~0u, v, mm);
        v = (lane & mm) ? (tt - v) : (tt + v);
    }
    #pragma unroll
    for (int off = 16; off; off >>= 1) {
        z5 += __shfl_xor_sync(~0u, z5, off);
        z6 += __shfl_xor_sync(~0u, z6, off);
        z7 += __shfl_xor_sync(~0u, z7, off);
    }
    float z[8];
    z[0] = __shfl_sync(~0u, v, 16);
    z[1] = __shfl_sync(~0u, v, 8);
    z[2] = __shfl_sync(~0u, v, 4);
    z[3] = __shfl_sync(~0u, v, 2);
    z[4] = __shfl_sync(~0u, v, 1);
    z[5] = z5; z[6] = z6; z[7] = z7;

    float logit = -1e30f;
    if (lane < 12) {
        logit = b_head[lane];
        #pragma unroll
        for (int k = 0; k < 8; k++) logit = fmaf(z[k], Whead[lane * 8 + k], logit);
    }
    float mx = logit;
    #pragma unroll
    for (int off = 8; off; off >>= 1) mx = fmaxf(mx, __shfl_xor_sync(~0u, mx, off, 16));
    float e = (lane < 12) ? __expf(logit - mx) : 0.f;
    float se = e;
    #pragma unroll
    for (int off = 8; off; off >>= 1) se += __shfl_xor_sync(~0u, se, off, 16);
    if (lane < 12) out[warp * T_OUT + lane] = logit - mx - __logf(se);
}

// ---------------------------------------------------------------------------
// Host: numpy-legacy MT19937 (RandomState(1234)) + gate fusion -> coefficients.
// ---------------------------------------------------------------------------
namespace {
struct MTState { uint32_t mt[624]; int mti; };

static void mt_seed(MTState& s, uint32_t seed) {
    s.mt[0] = seed;
    for (int i = 1; i < 624; i++)
        s.mt[i] = 1812433253u * (s.mt[i - 1] ^ (s.mt[i - 1] >> 30)) + (uint32_t)i;
    s.mti = 624;
}
static uint32_t mt_next(MTState& s) {
    if (s.mti >= 624) {
        for (int i = 0; i < 624; i++) {
            uint32_t y = (s.mt[i] & 0x80000000u) | (s.mt[(i + 1) % 624] & 0x7fffffffu);
            s.mt[i] = s.mt[(i + 397) % 624] ^ (y >> 1) ^ ((y & 1u) ? 0x9908b0dfu : 0u);
        }
        s.mti = 0;
    }
    uint32_t y = s.mt[s.mti++];
    y ^= y >> 11;
    y ^= (y << 7) & 0x9d2c5680u;
    y ^= (y << 15) & 0xefc60000u;
    y ^= y >> 18;
    return y;
}
static uint32_t np_randint(MTState& s, uint32_t n) {
    uint32_t rng = n - 1;
    uint32_t mask = rng;
    mask |= mask >> 1; mask |= mask >> 2; mask |= mask >> 4;
    mask |= mask >> 8; mask |= mask >> 16;
    uint32_t v;
    do { v = mt_next(s) & mask; } while (v > rng);
    return v;
}
static double np_double(MTState& s) {
    uint32_t a = mt_next(s) >> 5;
    uint32_t b = mt_next(s) >> 6;
    return ((double)a * 67108864.0 + (double)b) / 9007199254740992.0;
}

typedef std::complex<double> cd;

struct Pend {
    cd m[2][2];
    int count;
    bool allrz;
    void reset() { m[0][0] = 1.0; m[0][1] = 0.0; m[1][0] = 0.0; m[1][1] = 1.0; count = 0; allrz = true; }
};

static void build_u(QU& P) {
    MTState m;
    mt_seed(m, 1234u);

    Pend pend[8];
    for (int w = 0; w < 8; w++) pend[w].reset();
    int n = 0;

    auto flush = [&](int w) {
        if (!pend[w].count) return;
        float* u = &P.u[n * 8];
        if (pend[w].allrz) {
            u[0] = (float)pend[w].m[0][0].real();
            u[1] = (float)(-pend[w].m[0][0].imag());
        } else {
            u[0] = (float)pend[w].m[0][0].real(); u[1] = (float)pend[w].m[0][0].imag();
            u[2] = (float)pend[w].m[0][1].real(); u[3] = (float)pend[w].m[0][1].imag();
            u[4] = (float)pend[w].m[1][0].real(); u[5] = (float)pend[w].m[1][0].imag();
            u[6] = (float)pend[w].m[1][1].real(); u[7] = (float)pend[w].m[1][1].imag();
        }
        n++;
        pend[w].reset();
    };

    for (int k = 0; k < N_RAW; k++) {
        uint32_t kind = np_randint(m, 4);
        if (kind == 3) {
            int c = (int)np_randint(m, 8);
            int t = (int)np_randint(m, 7);
            if (t >= c) t++;
            flush(c); flush(t);
            n++;                       // CNOT slot (no coefficients)
        } else {
            int g = (int)(kind % 3);
            int w = (int)np_randint(m, 8);
            double ang = 6.283185307179586 * np_double(m);
            double th = (double)(float)ang;
            double c = cos(th * 0.5), s = sin(th * 0.5);
            cd R[2][2];
            if (g == 0) {
                R[0][0] = c; R[0][1] = cd(0, -s);
                R[1][0] = cd(0, -s); R[1][1] = c;
            } else if (g == 1) {
                R[0][0] = c; R[0][1] = -s;
                R[1][0] = s; R[1][1] = c;
            } else {
                R[0][0] = cd(c, -s); R[0][1] = 0.0;
                R[1][0] = 0.0; R[1][1] = cd(c, s);
            }
            cd n00 = R[0][0] * pend[w].m[0][0] + R[0][1] * pend[w].m[1][0];
            cd n01 = R[0][0] * pend[w].m[0][1] + R[0][1] * pend[w].m[1][1];
            cd n10 = R[1][0] * pend[w].m[0][0] + R[1][1] * pend[w].m[1][0];
            cd n11 = R[1][0] * pend[w].m[0][1] + R[1][1] * pend[w].m[1][1];
            pend[w].m[0][0] = n00; pend[w].m[0][1] = n01;
            pend[w].m[1][0] = n10; pend[w].m[1][1] = n11;
            pend[w].count++;
            if (g != 2) pend[w].allrz = false;
        }
    }
    for (int w = 0; w < 8; w++) flush(w);
}
} // namespace

// ---------------------------------------------------------------------------
extern "C" void kernel_launch(void* const* d_in, const int* in_sizes, int n_in,
                              void* d_out, int out_size) {
    (void)in_sizes; (void)n_in; (void)out_size;
    const float* emb    = (const float*)d_in[0];
    const float* Win    = (const float*)d_in[1];
    const float* b_in   = (const float*)d_in[2];
    const float* phi    = (const float*)d_in[3];
    const float* Wout   = (const float*)d_in[4];
    const float* b_out  = (const float*)d_in[5];
    const float* phiq   = (const float*)d_in[6];
    const float* Whead  = (const float*)d_in[7];
    const float* b_head = (const float*)d_in[8];
    const int*   sent   = (const int*)d_in[9];

    QU P{};
    build_u(P);

    zx_kernel<<<NROWS / 32, 256>>>(emb, Win, b_in, phi, sent, phiq, P);
    scan_kernel<<<B_SZ, 32>>>(Win, Wout, b_out);
    head_kernel<<<NROWS / 4, 128>>>(phiq, Whead, b_head, (float*)d_out, P);
}

// round 16
// speedup vs baseline: 2.4461x; 1.1324x over previous
#include <cuda_runtime.h>
#include <cstdint>
#include <math.h>
#include <complex>

// Problem constants
#define S_LEN 128
#define B_SZ  128
#define H_DIM 8
#define T_OUT 12
#define NROWS (S_LEN * B_SZ)
#define N_RAW 30
#define MAX_EMIT 40

// ---------------------------------------------------------------------------
// Device scratch
// ---------------------------------------------------------------------------
__device__ float g_zx[NROWS * 32];
__device__ float g_h[NROWS * H_DIM];
__device__ float g_fu[64];              // fused RX(phiq)*U coefficients per wire

struct QU { float u[MAX_EMIT * 8]; };   // fused-op coefficients, host-computed

// ---------------------------------------------------------------------------
// Compile-time MT19937 + random-layer structure (types/wires only; no floats).
// ---------------------------------------------------------------------------
struct EmitList { int n; int type[MAX_EMIT]; int a[MAX_EMIT]; int b[MAX_EMIT]; };

constexpr uint32_t cmt_next(uint32_t (&mt)[624], int& mti) {
    if (mti >= 624) {
        for (int i = 0; i < 624; i++) {
            uint32_t y = (mt[i] & 0x80000000u) | (mt[(i + 1) % 624] & 0x7fffffffu);
            mt[i] = mt[(i + 397) % 624] ^ (y >> 1) ^ ((y & 1u) ? 0x9908b0dfu : 0u);
        }
        mti = 0;
    }
    uint32_t y = mt[mti++];
    y ^= y >> 11;
    y ^= (y << 7) & 0x9d2c5680u;
    y ^= (y << 15) & 0xefc60000u;
    y ^= y >> 18;
    return y;
}
constexpr uint32_t c_randint(uint32_t (&mt)[624], int& mti, uint32_t n) {
    uint32_t rng = n - 1;
    uint32_t mask = rng;
    mask |= mask >> 1; mask |= mask >> 2; mask |= mask >> 4;
    mask |= mask >> 8; mask |= mask >> 16;
    uint32_t v = cmt_next(mt, mti) & mask;
    while (v > rng) v = cmt_next(mt, mti) & mask;
    return v;
}

constexpr EmitList compute_emitted() {
    uint32_t mt[624] = {};
    mt[0] = 1234u;
    for (int i = 1; i < 624; i++)
        mt[i] = 1812433253u * (mt[i - 1] ^ (mt[i - 1] >> 30)) + (uint32_t)i;
    int mti = 624;

    EmitList E{};
    int cnt[8] = {};
    bool allrz[8] = {true, true, true, true, true, true, true, true};

    for (int k = 0; k < N_RAW; k++) {
        uint32_t kind = c_randint(mt, mti, 4);
        if (kind == 3) {
            int c = (int)c_randint(mt, mti, 8);
            int t = (int)c_randint(mt, mti, 7);
            if (t >= c) t++;
            if (cnt[c]) { E.type[E.n] = allrz[c] ? 2 : 0; E.a[E.n] = c; E.b[E.n] = 0; E.n++; cnt[c] = 0; allrz[c] = true; }
            if (cnt[t]) { E.type[E.n] = allrz[t] ? 2 : 0; E.a[E.n] = t; E.b[E.n] = 0; E.n++; cnt[t] = 0; allrz[t] = true; }
            E.type[E.n] = 1; E.a[E.n] = c; E.b[E.n] = t; E.n++;
        } else {
            int g = (int)(kind % 3);
            int w = (int)c_randint(mt, mti, 8);
            cmt_next(mt, mti); cmt_next(mt, mti);   // uniform() draws
            cnt[w]++;
            if (g != 2) allrz[w] = false;
        }
    }
    for (int w = 0; w < 8; w++)
        if (cnt[w]) { E.type[E.n] = allrz[w] ? 2 : 0; E.a[E.n] = w; E.b[E.n] = 0; E.n++; }
    return E;
}

constexpr EmitList EM = compute_emitted();

// Fusion metadata as a constexpr VARIABLE (device-readable).
struct FuseInfo { int lastop[8]; bool fus[8]; int fuseat[MAX_EMIT]; };
constexpr FuseInfo compute_fuse() {
    FuseInfo F{};
    for (int w = 0; w < 8; w++) {
        int last = -1;
        for (int i = 0; i < EM.n; i++) {
            if (EM.type[i] == 1) { if (EM.a[i] == w || EM.b[i] == w) last = i; }
            else                 { if (EM.a[i] == w) last = i; }
        }
        F.lastop[w] = last;
        F.fus[w] = (last >= 0 && EM.type[last] != 1);
    }
    for (int o = 0; o < MAX_EMIT; o++) {
        F.fuseat[o] = -1;
        for (int w = 0; w < 8; w++)
            if (F.fus[w] && F.lastop[w] == o) F.fuseat[o] = w;
    }
    return F;
}
constexpr FuseInfo FI = compute_fuse();

// ---------------------------------------------------------------------------
// Fast helpers
// ---------------------------------------------------------------------------
__device__ __forceinline__ float fast_tanhm(float x){ float r; asm("tanh.approx.f32 %0,%1;":"=f"(r):"f"(x)); return r; }
__device__ __forceinline__ float fast_sigmoid_m(float x){ return fmaf(0.5f, fast_tanhm(0.5f * x), 0.5f); }

// ---------------------------------------------------------------------------
// RX(phiq) fusion: computed by zx_kernel block 0 / warp 7 (before head runs).
// ---------------------------------------------------------------------------
template <int W>
__device__ __forceinline__ void fuse_chain(int lane, const float* __restrict__ phiq,
                                           const float* __restrict__ U) {
    if constexpr (FI.fus[W]) {
        if (lane == W) {
            constexpr int O = FI.lastop[W];
            float s, c;
            __sincosf(phiq[W] * 0.5f, &s, &c);
            float u0, u1, u2, u3, u4, u5, u6, u7;
            if constexpr (EM.type[O] == 2) {
                float cz = U[O * 8 + 0], sz = U[O * 8 + 1];
                u0 = cz; u1 = -sz; u2 = 0.f; u3 = 0.f;
                u4 = 0.f; u5 = 0.f; u6 = cz; u7 = sz;
            } else {
                u0 = U[O * 8 + 0]; u1 = U[O * 8 + 1]; u2 = U[O * 8 + 2]; u3 = U[O * 8 + 3];
                u4 = U[O * 8 + 4]; u5 = U[O * 8 + 5]; u6 = U[O * 8 + 6]; u7 = U[O * 8 + 7];
            }
            g_fu[W * 8 + 0] = c * u0 + s * u5;
            g_fu[W * 8 + 1] = c * u1 - s * u4;
            g_fu[W * 8 + 2] = c * u2 + s * u7;
            g_fu[W * 8 + 3] = c * u3 - s * u6;
            g_fu[W * 8 + 4] = c * u4 + s * u1;
            g_fu[W * 8 + 5] = c * u5 - s * u0;
            g_fu[W * 8 + 6] = c * u6 + s * u3;
            g_fu[W * 8 + 7] = c * u7 - s * u2;
        }
    }
    if constexpr (W < 7) fuse_chain<W + 1>(lane, phiq, U);
}

// ---------------------------------------------------------------------------
// Kernel 1: zx (MLP=4 body) + RX fusion side-task.
// ---------------------------------------------------------------------------
__global__ __launch_bounds__(256) void zx_kernel(
    const float* __restrict__ emb, const float* __restrict__ Win,
    const float* __restrict__ b_in, const float* __restrict__ phi,
    const int* __restrict__ sent32, const float* __restrict__ phiq, QU P)
{
    __shared__ float4 sW4[32 * 17];
    __shared__ float4 sx4[32 * 17];
    __shared__ float  sBP[32];
    __shared__ int    sIs64;

    int tid = threadIdx.x, lane = tid & 31, wid = tid >> 5;

    if (wid == 0) {
        int acc = sent32[2 * lane + 1] | sent32[2 * (lane + 32) + 1];
        #pragma unroll
        for (int off = 16; off; off >>= 1) acc |= __shfl_xor_sync(~0u, acc, off);
        if (lane == 0) sIs64 = (acc == 0) ? 1 : 0;
    }
    if (blockIdx.x == 0 && wid == 7) fuse_chain<0>(lane, phiq, P.u);

    for (int i = tid; i < 512; i += 256) {
        int t = i >> 4, k = i & 15;
        sW4[t * 17 + k] = ((const float4*)(Win + t * 72))[k];
    }
    if (tid < 32) sBP[tid] = b_in[tid] + phi[tid];
    __syncthreads();

    int m0 = blockIdx.x * 32 + wid * 4;
    int r = lane >> 3;
    int kk = lane & 7;
    int m = m0 + r;
    int tok = sIs64 ? sent32[2 * m] : sent32[m];
    const float4* xsrc = (const float4*)(emb + (size_t)tok * 64);
    float4 v0 = xsrc[kk];
    float4 v1 = xsrc[kk + 8];
    sx4[(wid * 4 + r) * 17 + kk]     = v0;
    sx4[(wid * 4 + r) * 17 + kk + 8] = v1;
    __syncwarp();

    int t = lane;
    float bp = sBP[t];
    float a0[4], a1[4], a2[4], a3[4];
    #pragma unroll
    for (int j = 0; j < 4; j++) { a0[j] = bp; a1[j] = 0.f; a2[j] = 0.f; a3[j] = 0.f; }

    const float4* wr = &sW4[t * 17];
    const float4* x0 = &sx4[(wid * 4 + 0) * 17];
    const float4* x1 = &sx4[(wid * 4 + 1) * 17];
    const float4* x2 = &sx4[(wid * 4 + 2) * 17];
    const float4* x3 = &sx4[(wid * 4 + 3) * 17];
    #pragma unroll
    for (int k = 0; k < 16; k++) {
        float4 w  = wr[k];
        float4 b0 = x0[k], b1 = x1[k], b2 = x2[k], b3 = x3[k];
        a0[0] = fmaf(b0.x, w.x, a0[0]); a1[0] = fmaf(b0.y, w.y, a1[0]);
        a2[0] = fmaf(b0.z, w.z, a2[0]); a3[0] = fmaf(b0.w, w.w, a3[0]);
        a0[1] = fmaf(b1.x, w.x, a0[1]); a1[1] = fmaf(b1.y, w.y, a1[1]);
        a2[1] = fmaf(b1.z, w.z, a2[1]); a3[1] = fmaf(b1.w, w.w, a3[1]);
        a0[2] = fmaf(b2.x, w.x, a0[2]); a1[2] = fmaf(b2.y, w.y, a1[2]);
        a2[2] = fmaf(b2.z, w.z, a2[2]); a3[2] = fmaf(b2.w, w.w, a3[2]);
        a0[3] = fmaf(b3.x, w.x, a0[3]); a1[3] = fmaf(b3.y, w.y, a1[3]);
        a2[3] = fmaf(b3.z, w.z, a2[3]); a3[3] = fmaf(b3.w, w.w, a3[3]);
    }
    #pragma unroll
    for (int j = 0; j < 4; j++)
        g_zx[(m0 + j) * 32 + t] = (a0[j] + a1[j]) + (a2[j] + a3[j]);
}

// ---------------------------------------------------------------------------
// Kernel 2: sequential LSTM scan. Activations via MUFU.TANH:
//   sigma(x) = 0.5*tanh(x/2)+0.5 (identity), cell tanh direct.
// ---------------------------------------------------------------------------
__global__ __launch_bounds__(32) void scan_kernel(
    const float* __restrict__ Win, const float* __restrict__ Wout,
    const float* __restrict__ b_out)
{
    int b = blockIdx.x;
    int t = threadIdx.x;
    int g = t >> 3, q = t & 7;

    float wh[8], wo[8];
    #pragma unroll
    for (int j = 0; j < 8; j++) wh[j] = Win[t * 72 + 64 + j];
    #pragma unroll
    for (int j = 0; j < 8; j++) wo[j] = Wout[t * 8 + j];
    float bo = b_out[t];

    float h = 0.f, c = 0.f;
    float zn = g_zx[b * 32 + t];

    for (int s = 0; s < S_LEN; s++) {
        float z = zn;
        if (s + 1 < S_LEN) zn = g_zx[((s + 1) * B_SZ + b) * 32 + t];
        float h0 = __shfl_sync(~0u, h, 0), h1 = __shfl_sync(~0u, h, 1);
        float h2 = __shfl_sync(~0u, h, 2), h3 = __shfl_sync(~0u, h, 3);
        float h4 = __shfl_sync(~0u, h, 4), h5 = __shfl_sync(~0u, h, 5);
        float h6 = __shfl_sync(~0u, h, 6), h7 = __shfl_sync(~0u, h, 7);
        float a0 = fmaf(h0, wh[0], fmaf(h1, wh[1], fmaf(h2, wh[2], h3 * wh[3])));
        float a1 = fmaf(h4, wh[4], fmaf(h5, wh[5], fmaf(h6, wh[6], h7 * wh[7])));
        z = z + a0 + a1;

        float p = __cosf(z);
        float cj[8];
        #pragma unroll
        for (int j = 0; j < 8; j++) cj[j] = __shfl_sync(~0u, p, (g << 3) + j);
        float A = fmaf(cj[1], fmaf(cj[2], fmaf(cj[3], wo[3], wo[2]), wo[1]), wo[0]);
        float B = fmaf(cj[5], fmaf(cj[6], fmaf(cj[7], wo[7], wo[6]), wo[5]), wo[4]);
        float q01 = cj[0] * cj[1], q23 = cj[2] * cj[3];
        float Q = q01 * q23 * cj[4];
        float pre = fmaf(Q, B, fmaf(cj[0], A, bo));

        // g==2: tanh(pre); else sigma(pre) = 0.5*tanh(pre/2)+0.5 -- one MUFU each
        float xin = (g == 2) ? pre : 0.5f * pre;
        float tv = fast_tanhm(xin);
        float act = (g == 2) ? tv : fmaf(0.5f, tv, 0.5f);

        float af = __shfl_sync(~0u, act, q);
        float ii = __shfl_sync(~0u, act, 8 + q);
        float ag = __shfl_sync(~0u, act, 16 + q);
        float ao = __shfl_sync(~0u, act, 24 + q);
        c = fmaf(af, c, ii * ag);
        h = ao * fast_tanhm(c);
        if (t < 8) g_h[(s * B_SZ + b) * H_DIM + t] = h;
    }
}

// ---------------------------------------------------------------------------
// Quantum head primitives (compile-time specialized).
// ---------------------------------------------------------------------------
template <int LM>
__device__ __forceinline__ void u2_lane_t(float (&ar)[8], float (&ai)[8],
                                          int lane, const float* __restrict__ u) {
    int myb = (lane & LM) ? 1 : 0;
    float dr = myb ? u[6] : u[0];
    float di = myb ? u[7] : u[1];
    float orr= myb ? u[4] : u[2];
    float oi = myb ? u[5] : u[3];
    #pragma unroll
    for (int r = 0; r < 8; r++) {
        float pr = __shfl_xor_sync(~0u, ar[r], LM);
        float pi = __shfl_xor_sync(~0u, ai[r], LM);
        float nr = dr * ar[r] - di * ai[r] + orr * pr - oi * pi;
        float ni = dr * ai[r] + di * ar[r] + orr * pi + oi * pr;
        ar[r] = nr; ai[r] = ni;
    }
}

template <int TM>
__device__ __forceinline__ void u2_reg_t(float (&ar)[8], float (&ai)[8],
                                         const float* __restrict__ u) {
    #pragma unroll
    for (int r = 0; r < 8; r++) {
        if ((r & TM) == 0) {
            const int r1 = r | TM;
            float a0r = ar[r], a0i = ai[r], a1r = ar[r1], a1i = ai[r1];
            ar[r]  = u[0]*a0r - u[1]*a0i + u[2]*a1r - u[3]*a1i;
            ai[r]  = u[0]*a0i + u[1]*a0r + u[2]*a1i + u[3]*a1r;
            ar[r1] = u[4]*a0r - u[5]*a0i + u[6]*a1r - u[7]*a1i;
            ai[r1] = u[4]*a0i + u[5]*a0r + u[6]*a1i + u[7]*a1r;
        }
    }
}

template <int P>
__device__ __forceinline__ void rz_t(float (&ar)[8], float (&ai)[8],
                                     int lane, float c, float s) {
    #pragma unroll
    for (int r = 0; r < 8; r++) {
        bool beta;
        if constexpr (P >= 3) beta = (lane >> (P - 3)) & 1;
        else                  beta = (r >> P) & 1;
        float sg = beta ? -s : s;
        float nr = fmaf(c, ar[r],  sg * ai[r]);
        float ni = fmaf(c, ai[r], -sg * ar[r]);
        ar[r] = nr; ai[r] = ni;
    }
}

template <int CM, int TM>
__device__ __forceinline__ void cnot_rr_tt(float (&ar)[8], float (&ai)[8]) {
    #pragma unroll
    for (int r = 0; r < 8; r++) {
        if (((r & CM) != 0) && ((r & TM) == 0)) {
            const int r1 = r | TM;
            float tr = ar[r]; ar[r] = ar[r1]; ar[r1] = tr;
            float ti = ai[r]; ai[r] = ai[r1]; ai[r1] = ti;
        }
    }
}

template <int TM>
__device__ __forceinline__ void cnot_lr_tt(float (&ar)[8], float (&ai)[8], int ctrl) {
    #pragma unroll
    for (int r = 0; r < 8; r++) {
        if ((r & TM) == 0) {
            const int r1 = r | TM;
            float tr = ctrl ? ar[r1] : ar[r];
            float t2 = ctrl ? ar[r]  : ar[r1];
            ar[r] = tr; ar[r1] = t2;
            float ti = ctrl ? ai[r1] : ai[r];
            float t3 = ctrl ? ai[r]  : ai[r1];
            ai[r] = ti; ai[r1] = t3;
        }
    }
}

template <int CM, int LT>
__device__ __forceinline__ void cnot_rl_tt(float (&ar)[8], float (&ai)[8]) {
    #pragma unroll
    for (int r = 0; r < 8; r++) {
        if ((r & CM) != 0) {
            float sr = __shfl_xor_sync(~0u, ar[r], LT);
            float si = __shfl_xor_sync(~0u, ai[r], LT);
            ar[r] = sr; ai[r] = si;
        }
    }
}

template <int CM, int LT>
__device__ __forceinline__ void cnot_ll_tt(float (&ar)[8], float (&ai)[8], int lane) {
    int ctrl = (lane & CM) != 0;
    #pragma unroll
    for (int r = 0; r < 8; r++) {
        float sr = __shfl_xor_sync(~0u, ar[r], LT);
        float si = __shfl_xor_sync(~0u, ai[r], LT);
        if (ctrl) { ar[r] = sr; ai[r] = si; }
    }
}

template <int TM>
__device__ __forceinline__ void rx_reg(float (&ar)[8], float (&ai)[8], float c, float s) {
    #pragma unroll
    for (int r = 0; r < 8; r++) {
        if ((r & TM) == 0) {
            const int r1 = r | TM;
            float a0r = ar[r], a0i = ai[r], a1r = ar[r1], a1i = ai[r1];
            ar[r]  = fmaf(c, a0r,  s * a1i);  ai[r]  = fmaf(c, a0i, -s * a1r);
            ar[r1] = fmaf(c, a1r,  s * a0i);  ai[r1] = fmaf(c, a1i, -s * a0r);
        }
    }
}

template <int LM>
__device__ __forceinline__ void rx_lane(float (&ar)[8], float (&ai)[8], float c, float s) {
    #pragma unroll
    for (int r = 0; r < 8; r++) {
        float pr = __shfl_xor_sync(~0u, ar[r], LM);
        float pi = __shfl_xor_sync(~0u, ai[r], LM);
        float nr = fmaf(c, ar[r],  s * pi);
        float ni = fmaf(c, ai[r], -s * pr);
        ar[r] = nr; ai[r] = ni;
    }
}

// ---- fully unrolled random layer; fused final per-wire ops read g_fu ----
template <int O>
__device__ __forceinline__ void apply_all(float (&ar)[8], float (&ai)[8],
                                          int lane, const float* __restrict__ U) {
    if constexpr (O < EM.n) {
        constexpr int TY = EM.type[O];
        constexpr int A  = EM.a[O];
        constexpr int B  = EM.b[O];
        constexpr int FW = FI.fuseat[O];
        if constexpr (TY == 1) {
            constexpr int PC = 7 - A, PT = 7 - B;
            if constexpr (PT < 3) {
                if constexpr (PC < 3) cnot_rr_tt<(1 << PC), (1 << PT)>(ar, ai);
                else cnot_lr_tt<(1 << PT)>(ar, ai, (lane >> (PC - 3)) & 1);
            } else {
                if constexpr (PC < 3) cnot_rl_tt<(1 << PC), (1 << (PT - 3))>(ar, ai);
                else cnot_ll_tt<(1 << (PC - 3)), (1 << (PT - 3))>(ar, ai, lane);
            }
        } else if constexpr (FW >= 0) {
            constexpr int P_ = 7 - A;
            if constexpr (P_ < 3) u2_reg_t<(1 << P_)>(ar, ai, g_fu + FW * 8);
            else u2_lane_t<(1 << (P_ - 3))>(ar, ai, lane, g_fu + FW * 8);
        } else if constexpr (TY == 2) {
            rz_t<7 - A>(ar, ai, lane, U[O * 8 + 0], U[O * 8 + 1]);
        } else {
            constexpr int P_ = 7 - A;
            if constexpr (P_ < 3) u2_reg_t<(1 << P_)>(ar, ai, U + O * 8);
            else u2_lane_t<(1 << (P_ - 3))>(ar, ai, lane, U + O * 8);
        }
        apply_all<O + 1>(ar, ai, lane, U);
    }
}

// RX(phiq) only on wires NOT already fused into the circuit.
template <int W>
__device__ __forceinline__ void rx_chain(float (&ar)[8], float (&ai)[8],
                                         int lane, float pc, float ps) {
    if constexpr (!FI.fus[W]) {
        float cw = __shfl_sync(~0u, pc, W);
        float sw = __shfl_sync(~0u, ps, W);
        constexpr int P_ = 7 - W;
        if constexpr (P_ < 3) rx_reg<(1 << P_)>(ar, ai, cw, sw);
        else rx_lane<(1 << (P_ - 3))>(ar, ai, cw, sw);
    }
    if constexpr (W < 7) rx_chain<W + 1>(ar, ai, lane, pc, ps);
}

// ---------------------------------------------------------------------------
// Kernel 3: quantum head + log-softmax. One warp per output row.
// ---------------------------------------------------------------------------
__global__ __launch_bounds__(128) void head_kernel(
    const float* __restrict__ phiq, const float* __restrict__ Whead,
    const float* __restrict__ b_head, float* __restrict__ out, QU P)
{
    int warp = (blockIdx.x * blockDim.x + threadIdx.x) >> 5;
    int lane = threadIdx.x & 31;
    int s_out = warp >> 7, b_out = warp & 127;
    const float* hsrc = g_h + ((b_out << 7) + s_out) * H_DIM;

    float myc = 1.f, mys = 0.f;
    if (lane < 8) __sincosf(hsrc[lane] * 0.5f, &mys, &myc);
    float lp = 1.f;
    #pragma unroll
    for (int w = 0; w < 5; w++) {
        float cw = __shfl_sync(~0u, myc, w);
        float sw = __shfl_sync(~0u, mys, w);
        lp *= ((lane >> (4 - w)) & 1) ? sw : cw;
    }
    float c5 = __shfl_sync(~0u, myc, 5), s5 = __shfl_sync(~0u, mys, 5);
    float c6 = __shfl_sync(~0u, myc, 6), s6 = __shfl_sync(~0u, mys, 6);
    float c7 = __shfl_sync(~0u, myc, 7), s7 = __shfl_sync(~0u, mys, 7);

    float ar[8], ai[8];
    #pragma unroll
    for (int r = 0; r < 8; r++) {
        ar[r] = lp * ((r & 4) ? s5 : c5) * ((r & 2) ? s6 : c6) * ((r & 1) ? s7 : c7);
        ai[r] = 0.f;
    }

    apply_all<0>(ar, ai, lane, P.u);

    float pc = 1.f, ps = 0.f;
    if (lane < 8) __sincosf(phiq[lane] * 0.5f, &ps, &pc);
    rx_chain<0>(ar, ai, lane, pc, ps);

    float p[8], tot = 0.f;
    #pragma unroll
    for (int r = 0; r < 8; r++) {
        p[r] = ar[r] * ar[r] + ai[r] * ai[r];
        tot += p[r];
    }
    float z5 = (p[0] + p[1] + p[2] + p[3]) - (p[4] + p[5] + p[6] + p[7]);
    float z6 = (p[0] + p[1] + p[4] + p[5]) - (p[2] + p[3] + p[6] + p[7]);
    float z7 = (p[0] + p[2] + p[4] + p[6]) - (p[1] + p[3] + p[5] + p[7]);

    float v = tot;
    #pragma unroll
    for (int mm = 1; mm < 32; mm <<= 1) {
        float tt = __shfl_xor_sync(~0u, v, mm);
        v = (lane & mm) ? (tt - v) : (tt + v);
    }
    #pragma unroll
    for (int off = 16; off; off >>= 1) {
        z5 += __shfl_xor_sync(~0u, z5, off);
        z6 += __shfl_xor_sync(~0u, z6, off);
        z7 += __shfl_xor_sync(~0u, z7, off);
    }
    float z[8];
    z[0] = __shfl_sync(~0u, v, 16);
    z[1] = __shfl_sync(~0u, v, 8);
    z[2] = __shfl_sync(~0u, v, 4);
    z[3] = __shfl_sync(~0u, v, 2);
    z[4] = __shfl_sync(~0u, v, 1);
    z[5] = z5; z[6] = z6; z[7] = z7;

    // logits + log-softmax (|logit| is small; no max-shift needed in fp32)
    float logit = 0.f;
    float e = 0.f;
    if (lane < 12) {
        logit = b_head[lane];
        #pragma unroll
        for (int k = 0; k < 8; k++) logit = fmaf(z[k], Whead[lane * 8 + k], logit);
        e = __expf(logit);
    }
    float se = e;
    #pragma unroll
    for (int off = 8; off; off >>= 1) se += __shfl_xor_sync(~0u, se, off, 16);
    if (lane < 12) out[warp * T_OUT + lane] = logit - __logf(se);
}

// ---------------------------------------------------------------------------
// Host: numpy-legacy MT19937 (RandomState(1234)) + gate fusion -> coefficients.
// ---------------------------------------------------------------------------
namespace {
struct MTState { uint32_t mt[624]; int mti; };

static void mt_seed(MTState& s, uint32_t seed) {
    s.mt[0] = seed;
    for (int i = 1; i < 624; i++)
        s.mt[i] = 1812433253u * (s.mt[i - 1] ^ (s.mt[i - 1] >> 30)) + (uint32_t)i;
    s.mti = 624;
}
static uint32_t mt_next(MTState& s) {
    if (s.mti >= 624) {
        for (int i = 0; i < 624; i++) {
            uint32_t y = (s.mt[i] & 0x80000000u) | (s.mt[(i + 1) % 624] & 0x7fffffffu);
            s.mt[i] = s.mt[(i + 397) % 624] ^ (y >> 1) ^ ((y & 1u) ? 0x9908b0dfu : 0u);
        }
        s.mti = 0;
    }
    uint32_t y = s.mt[s.mti++];
    y ^= y >> 11;
    y ^= (y << 7) & 0x9d2c5680u;
    y ^= (y << 15) & 0xefc60000u;
    y ^= y >> 18;
    return y;
}
static uint32_t np_randint(MTState& s, uint32_t n) {
    uint32_t rng = n - 1;
    uint32_t mask = rng;
    mask |= mask >> 1; mask |= mask >> 2; mask |= mask >> 4;
    mask |= mask >> 8; mask |= mask >> 16;
    uint32_t v;
    do { v = mt_next(s) & mask; } while (v > rng);
    return v;
}
static double np_double(MTState& s) {
    uint32_t a = mt_next(s) >> 5;
    uint32_t b = mt_next(s) >> 6;
    return ((double)a * 67108864.0 + (double)b) / 9007199254740992.0;
}

typedef std::complex<double> cd;

struct Pend {
    cd m[2][2];
    int count;
    bool allrz;
    void reset() { m[0][0] = 1.0; m[0][1] = 0.0; m[1][0] = 0.0; m[1][1] = 1.0; count = 0; allrz = true; }
};

static void build_u(QU& P) {
    MTState m;
    mt_seed(m, 1234u);

    Pend pend[8];
    for (int w = 0; w < 8; w++) pend[w].reset();
    int n = 0;

    auto flush = [&](int w) {
        if (!pend[w].count) return;
        float* u = &P.u[n * 8];
        if (pend[w].allrz) {
            u[0] = (float)pend[w].m[0][0].real();
            u[1] = (float)(-pend[w].m[0][0].imag());
        } else {
            u[0] = (float)pend[w].m[0][0].real(); u[1] = (float)pend[w].m[0][0].imag();
            u[2] = (float)pend[w].m[0][1].real(); u[3] = (float)pend[w].m[0][1].imag();
            u[4] = (float)pend[w].m[1][0].real(); u[5] = (float)pend[w].m[1][0].imag();
            u[6] = (float)pend[w].m[1][1].real(); u[7] = (float)pend[w].m[1][1].imag();
        }
        n++;
        pend[w].reset();
    };

    for (int k = 0; k < N_RAW; k++) {
        uint32_t kind = np_randint(m, 4);
        if (kind == 3) {
            int c = (int)np_randint(m, 8);
            int t = (int)np_randint(m, 7);
            if (t >= c) t++;
            flush(c); flush(t);
            n++;                       // CNOT slot (no coefficients)
        } else {
            int g = (int)(kind % 3);
            int w = (int)np_randint(m, 8);
            double ang = 6.283185307179586 * np_double(m);
            double th = (double)(float)ang;
            double c = cos(th * 0.5), s = sin(th * 0.5);
            cd R[2][2];
            if (g == 0) {
                R[0][0] = c; R[0][1] = cd(0, -s);
                R[1][0] = cd(0, -s); R[1][1] = c;
            } else if (g == 1) {
                R[0][0] = c; R[0][1] = -s;
                R[1][0] = s; R[1][1] = c;
            } else {
                R[0][0] = cd(c, -s); R[0][1] = 0.0;
                R[1][0] = 0.0; R[1][1] = cd(c, s);
            }
            cd n00 = R[0][0] * pend[w].m[0][0] + R[0][1] * pend[w].m[1][0];
            cd n01 = R[0][0] * pend[w].m[0][1] + R[0][1] * pend[w].m[1][1];
            cd n10 = R[1][0] * pend[w].m[0][0] + R[1][1] * pend[w].m[1][0];
            cd n11 = R[1][0] * pend[w].m[0][1] + R[1][1] * pend[w].m[1][1];
            pend[w].m[0][0] = n00; pend[w].m[0][1] = n01;
            pend[w].m[1][0] = n10; pend[w].m[1][1] = n11;
            pend[w].count++;
            if (g != 2) pend[w].allrz = false;
        }
    }
    for (int w = 0; w < 8; w++) flush(w);
}
} // namespace

// ---------------------------------------------------------------------------
extern "C" void kernel_launch(void* const* d_in, const int* in_sizes, int n_in,
                              void* d_out, int out_size) {
    (void)in_sizes; (void)n_in; (void)out_size;
    const float* emb    = (const float*)d_in[0];
    const float* Win    = (const float*)d_in[1];
    const float* b_in   = (const float*)d_in[2];
    const float* phi    = (const float*)d_in[3];
    const float* Wout   = (const float*)d_in[4];
    const float* b_out  = (const float*)d_in[5];
    const float* phiq   = (const float*)d_in[6];
    const float* Whead  = (const float*)d_in[7];
    const float* b_head = (const float*)d_in[8];
    const int*   sent   = (const int*)d_in[9];

    QU P{};
    build_u(P);

    zx_kernel<<<NROWS / 32, 256>>>(emb, Win, b_in, phi, sent, phiq, P);
    scan_kernel<<<B_SZ, 32>>>(Win, Wout, b_out);
    head_kernel<<<NROWS / 4, 128>>>(phiq, Whead, b_head, (float*)d_out, P);
}